// round 13
// baseline (speedup 1.0000x reference)
#include <cuda_runtime.h>
#include <cuda_bf16.h>
#include <cstdint>
#include <math_constants.h>

#define E    1024
#define H    1024
#define SQ   4096
#define NB   2
#define MTOT 8192
#define NT   256
#define STAGE3    65536     // per-stage size (all GEMMs, 3 stages)
#define SMEM_G3   196608

// ---------------------------------------------------------------------------
// Device scratch (allocation-free per harness rules)
// ---------------------------------------------------------------------------
__device__ __align__(256) __nv_bfloat16 g_Xhi[(size_t)MTOT * E];
__device__ __align__(256) __nv_bfloat16 g_Xlo[(size_t)MTOT * E];
__device__ __align__(256) __nv_bfloat16 g_Whi[(size_t)3 * H * E];
__device__ __align__(256) __nv_bfloat16 g_Wlo[(size_t)3 * H * E];
__device__ __align__(256) __nv_bfloat16 g_Qhi[(size_t)MTOT * H];
__device__ __align__(256) __nv_bfloat16 g_Qlo[(size_t)MTOT * H];
__device__ __align__(256) __nv_bfloat16 g_Khi[(size_t)MTOT * H];
__device__ __align__(256) __nv_bfloat16 g_Klo[(size_t)MTOT * H];
__device__ __align__(256) __nv_bfloat16 g_Vthi[(size_t)NB * H * SQ]; // [b][h][s]
__device__ __align__(256) __nv_bfloat16 g_Vtlo[(size_t)NB * H * SQ];
__device__ __align__(256) float         g_P  [(size_t)NB * SQ * SQ];
__device__ __align__(256) __nv_bfloat16 g_Phi[(size_t)NB * SQ * SQ];
__device__ __align__(256) __nv_bfloat16 g_Plo[(size_t)NB * SQ * SQ];

// ---------------------------------------------------------------------------
// Helpers
// ---------------------------------------------------------------------------
__device__ __forceinline__ uint32_t smem_u32(const void* p) {
    uint32_t a;
    asm("{ .reg .u64 t; cvta.to.shared.u64 t, %1; cvt.u32.u64 %0, t; }"
        : "=r"(a) : "l"(p));
    return a;
}

#define SWZ(o) ((o) ^ (((o) >> 3) & 0x70))

__device__ __forceinline__ void cpa16(uint32_t dst, const void* src) {
    asm volatile("cp.async.cg.shared.global [%0], [%1], 16;" :: "r"(dst), "l"(src));
}
#define CP_COMMIT() asm volatile("cp.async.commit_group;" ::: "memory")
#define CP_WAIT2()  asm volatile("cp.async.wait_group 2;" ::: "memory")

__device__ __forceinline__ void ldsm4(uint32_t r[4], uint32_t addr) {
    asm volatile("ldmatrix.sync.aligned.m8n8.x4.shared.b16 {%0,%1,%2,%3}, [%4];"
                 : "=r"(r[0]), "=r"(r[1]), "=r"(r[2]), "=r"(r[3]) : "r"(addr));
}

__device__ __forceinline__ void mma16816(float* d, const uint32_t* a,
                                         uint32_t b0, uint32_t b1) {
    asm volatile(
        "mma.sync.aligned.m16n8k16.row.col.f32.bf16.bf16.f32 "
        "{%0,%1,%2,%3}, {%4,%5,%6,%7}, {%8,%9}, {%0,%1,%2,%3};"
        : "+f"(d[0]), "+f"(d[1]), "+f"(d[2]), "+f"(d[3])
        : "r"(a[0]), "r"(a[1]), "r"(a[2]), "r"(a[3]), "r"(b0), "r"(b1));
}

__device__ __forceinline__ void split2(float a, float b,
                                       __nv_bfloat162& h, __nv_bfloat162& l2) {
    h = __float22bfloat162_rn(make_float2(a, b));
    float2 hf = __bfloat1622float2(h);
    l2 = __float22bfloat162_rn(make_float2(a - hf.x, b - hf.y));
}

// Copy one 128x64 bf16 tile (K-major) into SW128-swizzled smem
__device__ __forceinline__ void fill_copy(uint32_t dst,
                                          const __nv_bfloat16* __restrict__ src,
                                          size_t ld, int tid) {
    #pragma unroll
    for (int i = 0; i < 4; i++) {
        int s = tid + i * NT;
        int r = s >> 3, q = s & 7;
        cpa16(dst + SWZ((uint32_t)(r * 128 + q * 16)),
              src + (size_t)r * ld + q * 8);
    }
}

// bf16x3 MMA work for one 128x128 x K64 block.
// Stage layout: Ahi @0, Alo @16384, Bhi @32768, Blo @49152 (16KB each).
__device__ __forceinline__ void mma_k64(uint32_t base, uint32_t aoff,
                                        uint32_t boff, float (&acc)[2][8][4]) {
    #pragma unroll
    for (int c = 0; c < 4; c++) {
        uint32_t ao = 32u * c;
        uint32_t ahi[2][4], alo[2][4], bhi[4][4], blo[4][4];
        ldsm4(ahi[0], base +         SWZ(aoff + ao));
        ldsm4(ahi[1], base +         SWZ(aoff + 2048 + ao));
        ldsm4(alo[0], base + 16384 + SWZ(aoff + ao));
        ldsm4(alo[1], base + 16384 + SWZ(aoff + 2048 + ao));
        #pragma unroll
        for (int j = 0; j < 4; j++) {
            ldsm4(bhi[j], base + 32768 + SWZ(boff + j * 2048 + ao));
            ldsm4(blo[j], base + 49152 + SWZ(boff + j * 2048 + ao));
        }
        #pragma unroll
        for (int j = 0; j < 4; j++)
            #pragma unroll
            for (int mf = 0; mf < 2; mf++) {
                mma16816(acc[mf][2*j],     ahi[mf], bhi[j][0], bhi[j][1]);
                mma16816(acc[mf][2*j + 1], ahi[mf], bhi[j][2], bhi[j][3]);
            }
        #pragma unroll
        for (int j = 0; j < 4; j++)
            #pragma unroll
            for (int mf = 0; mf < 2; mf++) {
                mma16816(acc[mf][2*j],     ahi[mf], blo[j][0], blo[j][1]);
                mma16816(acc[mf][2*j + 1], ahi[mf], blo[j][2], blo[j][3]);
            }
        #pragma unroll
        for (int j = 0; j < 4; j++)
            #pragma unroll
            for (int mf = 0; mf < 2; mf++) {
                mma16816(acc[mf][2*j],     alo[mf], bhi[j][0], bhi[j][1]);
                mma16816(acc[mf][2*j + 1], alo[mf], bhi[j][2], bhi[j][3]);
            }
    }
}

// ---------------------------------------------------------------------------
// Split fp32 -> (hi, lo) bf16. Region 0 = X, regions 1..3 = Wq/Wk/Wv.
// ---------------------------------------------------------------------------
__global__ __launch_bounds__(NT) void split_k(const float* __restrict__ X,
                                              const float* __restrict__ Wq,
                                              const float* __restrict__ Wk,
                                              const float* __restrict__ Wv,
                                              __nv_bfloat16* __restrict__ Xhi,
                                              __nv_bfloat16* __restrict__ Xlo,
                                              __nv_bfloat16* __restrict__ Whi,
                                              __nv_bfloat16* __restrict__ Wlo)
{
    const int nx = MTOT * E / 4;
    const int nw = H * E / 4;
    int i = blockIdx.x * NT + threadIdx.x;
    const float* src;
    __nv_bfloat16 *hi, *lo;
    int j;
    if (i < nx) {
        src = X; hi = Xhi; lo = Xlo; j = i;
    } else {
        int t = i - nx;
        int w = t / nw;
        j = t - w * nw;
        src = (w == 0) ? Wq : (w == 1) ? Wk : Wv;
        hi = Whi + (size_t)w * H * E;
        lo = Wlo + (size_t)w * H * E;
    }
    float4 v = ((const float4*)src)[j];
    __nv_bfloat162 h0, l0, h1, l1;
    split2(v.x, v.y, h0, l0);
    split2(v.z, v.w, h1, l1);
    ((__nv_bfloat162*)hi)[2 * j]     = h0;
    ((__nv_bfloat162*)hi)[2 * j + 1] = h1;
    ((__nv_bfloat162*)lo)[2 * j]     = l0;
    ((__nv_bfloat162*)lo)[2 * j + 1] = l1;
}

// ---------------------------------------------------------------------------
// QKV: persistent 3-stage streamed GEMM (R8 pipeline).
// Tiles: t = z*512 + row*8 + col; z in {Q,K,V}.
// z<2: direct register epilogue. z==2: V^T via free-stage smem transpose.
// ---------------------------------------------------------------------------
__global__ __launch_bounds__(NT) void qkv_mm(const float* __restrict__ bq,
                                             const float* __restrict__ bk,
                                             const float* __restrict__ bv)
{
    extern __shared__ char dsm[];
    uint32_t sbuf = smem_u32(dsm);
    const int tid = threadIdx.x, l = tid & 31, wid = tid >> 5;
    const int mw = (wid >> 1) * 32, nw = (wid & 1) * 64;
    const uint32_t aoff = (uint32_t)((mw + (l & 15)) * 128 + ((l >> 4) & 1) * 16);
    const uint32_t boff = (uint32_t)((nw + (l & 7) + ((l >> 4) & 1) * 8) * 128 +
                                     ((l >> 3) & 1) * 16);
    const int G = gridDim.x;
    const int NTILES = 3 * (MTOT / 128) * (H / 128);   // 1536
    const int NKB = E / 64;                             // 16

    int t_f = blockIdx.x, kb_f = 0, fp = 0;

    auto fill_step = [&]() {
        if (t_f < NTILES) {
            int z = t_f / 512, rem = t_f - z * 512;
            int row0 = (rem >> 3) << 7, col0 = (rem & 7) << 7;
            size_t ko = (size_t)kb_f * 64;
            const __nv_bfloat16* Bh = g_Whi + ((size_t)z * H + col0) * E + ko;
            const __nv_bfloat16* Bl = g_Wlo + ((size_t)z * H + col0) * E + ko;
            uint32_t b = sbuf + (uint32_t)(fp % 3) * STAGE3;
            fill_copy(b,         g_Xhi + (size_t)row0 * E + ko, E, tid);
            fill_copy(b + 16384, g_Xlo + (size_t)row0 * E + ko, E, tid);
            fill_copy(b + 32768, Bh, E, tid);
            fill_copy(b + 49152, Bl, E, tid);
        }
        CP_COMMIT();
        fp++;
        if (++kb_f == NKB) { kb_f = 0; t_f += G; }
    };
    fill_step();
    fill_step();

    float acc[2][8][4] = {};
    int cp = 0;
    const int r0 = mw + (l >> 2), c0 = nw + (l & 3) * 2;

    for (int t = blockIdx.x; t < NTILES; t += G) {
        for (int kb = 0; kb < NKB; kb++) {
            fill_step();
            CP_WAIT2();
            __syncthreads();
            mma_k64(sbuf + (uint32_t)(cp % 3) * STAGE3, aoff, boff, acc);
            __syncthreads();
            cp++;
        }
        int z = t / 512, rem = t - z * 512;
        int row0 = (rem >> 3) << 7, col0 = (rem & 7) << 7;
        const float* bias = (z == 0) ? bq : (z == 1) ? bk : bv;

        if (z < 2) {
            // Direct register epilogue (coalesced bf162 pairs)
            __nv_bfloat16* ohi = (z == 0) ? g_Qhi : g_Khi;
            __nv_bfloat16* olo = (z == 0) ? g_Qlo : g_Klo;
            #pragma unroll
            for (int mf = 0; mf < 2; mf++)
                #pragma unroll
                for (int nf = 0; nf < 8; nf++)
                    #pragma unroll
                    for (int hh = 0; hh < 2; hh++) {
                        int r = row0 + r0 + mf * 16 + hh * 8;
                        int c = col0 + c0 + nf * 8;
                        float a = acc[mf][nf][hh*2]     + __ldg(&bias[c]);
                        float b = acc[mf][nf][hh*2 + 1] + __ldg(&bias[c + 1]);
                        __nv_bfloat162 h, l2;
                        split2(a, b, h, l2);
                        size_t idx = ((size_t)r * H + c) >> 1;
                        ((__nv_bfloat162*)ohi)[idx] = h;
                        ((__nv_bfloat162*)olo)[idx] = l2;
                        acc[mf][nf][hh*2] = 0.0f;
                        acc[mf][nf][hh*2 + 1] = 0.0f;
                    }
        } else {
            // V^T epilogue: transpose through the FREE pipeline stage.
            // In-flight fill groups cp, cp+1 occupy stages cp%3, (cp+1)%3;
            // stage (cp+2)%3 was just consumed by the last mma (trailing sync
            // above guarantees all threads done). Two half-tile passes of
            // 64 cols x 128 rows fp32 (64*132*4 = 33.8KB <= 64KB stage).
            float* scr = (float*)(dsm + (size_t)((cp + 2) % 3) * STAGE3);
            int bb = row0 >> 12, s0base = row0 & 4095;
            #pragma unroll
            for (int p = 0; p < 2; p++) {
                if ((wid & 1) == p) {
                    #pragma unroll
                    for (int mf = 0; mf < 2; mf++)
                        #pragma unroll
                        for (int nf = 0; nf < 8; nf++)
                            #pragma unroll
                            for (int hh = 0; hh < 2; hh++) {
                                int crel = (l & 3) * 2 + nf * 8;
                                int r = mw + (l >> 2) + mf * 16 + hh * 8;
                                scr[crel * 132 + r]       = acc[mf][nf][hh*2];
                                scr[(crel + 1) * 132 + r] = acc[mf][nf][hh*2 + 1];
                                acc[mf][nf][hh*2] = 0.0f;
                                acc[mf][nf][hh*2 + 1] = 0.0f;
                            }
                }
                __syncthreads();
                #pragma unroll
                for (int i = 0; i < 16; i++) {
                    int s = tid + i * NT;             // 0..4095 pair slots
                    int hcol = s >> 6, sp = (s & 63) * 2;
                    int hg = col0 + p * 64 + hcol;
                    float bs = __ldg(&bias[hg]);
                    float a = scr[hcol * 132 + sp]     + bs;
                    float b = scr[hcol * 132 + sp + 1] + bs;
                    __nv_bfloat162 h, l2;
                    split2(a, b, h, l2);
                    size_t idx = (((size_t)bb * H + hg) * SQ + s0base + sp) >> 1;
                    ((__nv_bfloat162*)g_Vthi)[idx] = h;
                    ((__nv_bfloat162*)g_Vtlo)[idx] = l2;
                }
                __syncthreads();   // reads done before next pass / next fill
            }
        }
    }
}

// ---------------------------------------------------------------------------
// Scores: persistent 3-stage streamed GEMM (R8 form, verbatim).
// ---------------------------------------------------------------------------
__global__ __launch_bounds__(NT) void scores_mm(const int* __restrict__ mask)
{
    extern __shared__ char dsm[];
    uint32_t sbuf = smem_u32(dsm);
    const int tid = threadIdx.x, l = tid & 31, wid = tid >> 5;
    const int mw = (wid >> 1) * 32, nw = (wid & 1) * 64;
    const uint32_t aoff = (uint32_t)((mw + (l & 15)) * 128 + ((l >> 4) & 1) * 16);
    const uint32_t boff = (uint32_t)((nw + (l & 7) + ((l >> 4) & 1) * 8) * 128 +
                                     ((l >> 3) & 1) * 16);
    const int G = gridDim.x;
    const int NTILES = (SQ / 128) * (SQ / 128) * NB;   // 2048
    const int NKB = H / 64;                             // 16

    int t_f = blockIdx.x, kb_f = 0, fp = 0;

    auto fill_step = [&]() {
        if (t_f < NTILES) {
            int bz = t_f >> 10, rem = t_f & 1023;
            int row0 = (rem >> 5) << 7, col0 = (rem & 31) << 7;
            size_t ko = (size_t)kb_f * 64;
            uint32_t b = sbuf + (uint32_t)(fp % 3) * STAGE3;
            fill_copy(b,         g_Qhi + ((size_t)(bz * SQ + row0)) * H + ko, H, tid);
            fill_copy(b + 16384, g_Qlo + ((size_t)(bz * SQ + row0)) * H + ko, H, tid);
            fill_copy(b + 32768, g_Khi + ((size_t)(bz * SQ + col0)) * H + ko, H, tid);
            fill_copy(b + 49152, g_Klo + ((size_t)(bz * SQ + col0)) * H + ko, H, tid);
        }
        CP_COMMIT();
        fp++;
        if (++kb_f == NKB) { kb_f = 0; t_f += G; }
    };
    fill_step();
    fill_step();

    float acc[2][8][4] = {};
    int cp = 0;
    const float scale = 0.03125f;  // 1/sqrt(1024)
    const int r0 = mw + (l >> 2), c0 = nw + (l & 3) * 2;

    for (int t = blockIdx.x; t < NTILES; t += G) {
        for (int kb = 0; kb < NKB; kb++) {
            fill_step();
            CP_WAIT2();
            __syncthreads();
            mma_k64(sbuf + (uint32_t)(cp % 3) * STAGE3, aoff, boff, acc);
            __syncthreads();
            cp++;
        }
        int bz = t >> 10, rem = t & 1023;
        int row0 = (rem >> 5) << 7, col0 = (rem & 31) << 7;
        const size_t pbase = (size_t)bz * SQ * SQ;
        #pragma unroll
        for (int mf = 0; mf < 2; mf++)
            #pragma unroll
            for (int nf = 0; nf < 8; nf++)
                #pragma unroll
                for (int hh = 0; hh < 2; hh++) {
                    int r = row0 + r0 + mf * 16 + hh * 8;
                    int c = col0 + c0 + nf * 8;
                    size_t gi = pbase + (size_t)r * SQ + c;
                    int2 mk = __ldg((const int2*)(mask + gi));
                    float2 v;
                    v.x = (mk.x == 0) ? -CUDART_INF_F : acc[mf][nf][hh*2]     * scale;
                    v.y = (mk.y == 0) ? -CUDART_INF_F : acc[mf][nf][hh*2 + 1] * scale;
                    *(float2*)(g_P + gi) = v;
                    acc[mf][nf][hh*2] = 0.0f;
                    acc[mf][nf][hh*2 + 1] = 0.0f;
                }
    }
}

// ---------------------------------------------------------------------------
// Row softmax of g_P -> split bf16 P. One block per row; row in registers.
// ---------------------------------------------------------------------------
__global__ __launch_bounds__(256) void softmax_k()
{
    __shared__ float red[8];
    const int tid = threadIdx.x;
    const float* p = g_P + (size_t)blockIdx.x * SQ;

    float4 v[4];
    float m = -CUDART_INF_F;
    #pragma unroll
    for (int i = 0; i < 4; i++) {
        v[i] = __ldg((const float4*)(p + (size_t)(i * 256 + tid) * 4));
        m = fmaxf(m, fmaxf(fmaxf(v[i].x, v[i].y), fmaxf(v[i].z, v[i].w)));
    }
    #pragma unroll
    for (int o = 16; o; o >>= 1) m = fmaxf(m, __shfl_xor_sync(0xFFFFFFFFu, m, o));
    if ((tid & 31) == 0) red[tid >> 5] = m;
    __syncthreads();
    m = fmaxf(fmaxf(fmaxf(red[0], red[1]), fmaxf(red[2], red[3])),
              fmaxf(fmaxf(red[4], red[5]), fmaxf(red[6], red[7])));
    __syncthreads();

    float s = 0.0f;
    #pragma unroll
    for (int i = 0; i < 4; i++) {
        v[i].x = __expf(v[i].x - m); v[i].y = __expf(v[i].y - m);
        v[i].z = __expf(v[i].z - m); v[i].w = __expf(v[i].w - m);
        s += (v[i].x + v[i].y) + (v[i].z + v[i].w);
    }
    #pragma unroll
    for (int o = 16; o; o >>= 1) s += __shfl_xor_sync(0xFFFFFFFFu, s, o);
    if ((tid & 31) == 0) red[tid >> 5] = s;
    __syncthreads();
    s = ((red[0] + red[1]) + (red[2] + red[3])) +
        ((red[4] + red[5]) + (red[6] + red[7]));
    float inv = 1.0f / s;

    size_t r2 = (size_t)blockIdx.x * (SQ / 2);
    #pragma unroll
    for (int i = 0; i < 4; i++) {
        int base = (i * 256 + tid) * 2;
        __nv_bfloat162 h0, l0, h1, l1;
        split2(v[i].x * inv, v[i].y * inv, h0, l0);
        split2(v[i].z * inv, v[i].w * inv, h1, l1);
        ((__nv_bfloat162*)g_Phi)[r2 + base]     = h0;
        ((__nv_bfloat162*)g_Phi)[r2 + base + 1] = h1;
        ((__nv_bfloat162*)g_Plo)[r2 + base]     = l0;
        ((__nv_bfloat162*)g_Plo)[r2 + base + 1] = l1;
    }
}

// ---------------------------------------------------------------------------
// PV: persistent 3-stage streamed GEMM (R8 form, N=128 tiles, verbatim).
// ---------------------------------------------------------------------------
__global__ __launch_bounds__(NT) void pv_mm(float* __restrict__ out)
{
    extern __shared__ char dsm[];
    uint32_t sbuf = smem_u32(dsm);
    const int tid = threadIdx.x, l = tid & 31, wid = tid >> 5;
    const int mw = (wid >> 1) * 32, nw = (wid & 1) * 64;
    const uint32_t aoff = (uint32_t)((mw + (l & 15)) * 128 + ((l >> 4) & 1) * 16);
    const uint32_t boff = (uint32_t)((nw + (l & 7) + ((l >> 4) & 1) * 8) * 128 +
                                     ((l >> 3) & 1) * 16);
    const int G = gridDim.x;
    const int NTILES = (H / 128) * (SQ / 128) * NB;   // 512
    const int NKB = SQ / 64;                           // 64

    int t_f = blockIdx.x, kb_f = 0, fp = 0;

    auto fill_step = [&]() {
        if (t_f < NTILES) {
            int bz = t_f >> 8, rem = t_f & 255;
            int row0 = (rem >> 3) << 7, col0 = (rem & 7) << 7;
            size_t ko = (size_t)kb_f * 64;
            uint32_t b = sbuf + (uint32_t)(fp % 3) * STAGE3;
            fill_copy(b,         g_Phi + (size_t)bz * SQ * SQ +
                                 (size_t)row0 * SQ + ko, SQ, tid);
            fill_copy(b + 16384, g_Plo + (size_t)bz * SQ * SQ +
                                 (size_t)row0 * SQ + ko, SQ, tid);
            fill_copy(b + 32768, g_Vthi + ((size_t)bz * H + col0) * SQ + ko, SQ, tid);
            fill_copy(b + 49152, g_Vtlo + ((size_t)bz * H + col0) * SQ + ko, SQ, tid);
        }
        CP_COMMIT();
        fp++;
        if (++kb_f == NKB) { kb_f = 0; t_f += G; }
    };
    fill_step();
    fill_step();

    float acc[2][8][4] = {};
    int cp = 0;
    const int r0 = mw + (l >> 2), c0 = nw + (l & 3) * 2;

    for (int t = blockIdx.x; t < NTILES; t += G) {
        for (int kb = 0; kb < NKB; kb++) {
            fill_step();
            CP_WAIT2();
            __syncthreads();
            mma_k64(sbuf + (uint32_t)(cp % 3) * STAGE3, aoff, boff, acc);
            __syncthreads();
            cp++;
        }
        int bz = t >> 8, rem = t & 255;
        int row0 = (rem >> 3) << 7, col0 = (rem & 7) << 7;
        #pragma unroll
        for (int mf = 0; mf < 2; mf++)
            #pragma unroll
            for (int nf = 0; nf < 8; nf++)
                #pragma unroll
                for (int hh = 0; hh < 2; hh++) {
                    int r = row0 + r0 + mf * 16 + hh * 8;
                    int c = col0 + c0 + nf * 8;
                    float2 v = make_float2(acc[mf][nf][hh*2], acc[mf][nf][hh*2 + 1]);
                    *(float2*)&out[((size_t)bz * SQ + r) * H + c] = v;
                    acc[mf][nf][hh*2] = 0.0f;
                    acc[mf][nf][hh*2 + 1] = 0.0f;
                }
    }
}

// ---------------------------------------------------------------------------
extern "C" void kernel_launch(void* const* d_in, const int* in_sizes, int n_in,
                              void* d_out, int out_size)
{
    const float* X    = (const float*)d_in[0];
    const int*   mask = (const int*)  d_in[1];
    const float* Wq   = (const float*)d_in[2];
    const float* bq   = (const float*)d_in[3];
    const float* Wk   = (const float*)d_in[4];
    const float* bk   = (const float*)d_in[5];
    const float* Wv   = (const float*)d_in[6];
    const float* bv   = (const float*)d_in[7];
    float* out = (float*)d_out;

    cudaFuncSetAttribute(qkv_mm,    cudaFuncAttributeMaxDynamicSharedMemorySize, SMEM_G3);
    cudaFuncSetAttribute(scores_mm, cudaFuncAttributeMaxDynamicSharedMemorySize, SMEM_G3);
    cudaFuncSetAttribute(pv_mm,     cudaFuncAttributeMaxDynamicSharedMemorySize, SMEM_G3);

    int dev = 0, nsm = 148;
    cudaGetDevice(&dev);
    cudaDeviceGetAttribute(&nsm, cudaDevAttrMultiProcessorCount, dev);

    __nv_bfloat16 *pXhi, *pXlo, *pWhi, *pWlo;
    cudaGetSymbolAddress((void**)&pXhi, g_Xhi);
    cudaGetSymbolAddress((void**)&pXlo, g_Xlo);
    cudaGetSymbolAddress((void**)&pWhi, g_Whi);
    cudaGetSymbolAddress((void**)&pWlo, g_Wlo);

    int total4 = (MTOT * E + 3 * H * E) / 4;
    split_k<<<total4 / NT, NT>>>(X, Wq, Wk, Wv, pXhi, pXlo, pWhi, pWlo);

    qkv_mm<<<nsm, NT, SMEM_G3>>>(bq, bk, bv);
    scores_mm<<<nsm, NT, SMEM_G3>>>(mask);
    softmax_k<<<NB * SQ, 256>>>();
    pv_mm<<<nsm, NT, SMEM_G3>>>(out);
}

// round 14
// speedup vs baseline: 1.0458x; 1.0458x over previous
#include <cuda_runtime.h>
#include <cuda_bf16.h>
#include <cstdint>
#include <math_constants.h>

#define E    1024
#define H    1024
#define SQ   4096
#define NB   2
#define MTOT 8192
#define NT   256
#define STAGE2    65536     // 2-stage buffer size (qkv)
#define SMEM_QKV  131072
#define STAGE3    65536     // per-stage size, 3-stage kernels
#define SMEM_S3   196608

// ---------------------------------------------------------------------------
// Device scratch (allocation-free per harness rules)
// ---------------------------------------------------------------------------
__device__ __align__(256) __nv_bfloat16 g_Xhi[(size_t)MTOT * E];
__device__ __align__(256) __nv_bfloat16 g_Xlo[(size_t)MTOT * E];
__device__ __align__(256) __nv_bfloat16 g_Whi[(size_t)3 * H * E];
__device__ __align__(256) __nv_bfloat16 g_Wlo[(size_t)3 * H * E];
__device__ __align__(256) __nv_bfloat16 g_Qhi[(size_t)MTOT * H];
__device__ __align__(256) __nv_bfloat16 g_Qlo[(size_t)MTOT * H];
__device__ __align__(256) __nv_bfloat16 g_Khi[(size_t)MTOT * H];
__device__ __align__(256) __nv_bfloat16 g_Klo[(size_t)MTOT * H];
__device__ __align__(256) __nv_bfloat16 g_Vthi[(size_t)NB * H * SQ]; // [b][h][s]
__device__ __align__(256) __nv_bfloat16 g_Vtlo[(size_t)NB * H * SQ];
__device__ __align__(256) float         g_P  [(size_t)NB * SQ * SQ];
__device__ __align__(256) __nv_bfloat16 g_Phi[(size_t)NB * SQ * SQ];
__device__ __align__(256) __nv_bfloat16 g_Plo[(size_t)NB * SQ * SQ];

// ---------------------------------------------------------------------------
// Helpers
// ---------------------------------------------------------------------------
__device__ __forceinline__ uint32_t smem_u32(const void* p) {
    uint32_t a;
    asm("{ .reg .u64 t; cvta.to.shared.u64 t, %1; cvt.u32.u64 %0, t; }"
        : "=r"(a) : "l"(p));
    return a;
}

#define SWZ(o) ((o) ^ (((o) >> 3) & 0x70))

__device__ __forceinline__ void cpa16(uint32_t dst, const void* src) {
    asm volatile("cp.async.cg.shared.global [%0], [%1], 16;" :: "r"(dst), "l"(src));
}
#define CP_COMMIT() asm volatile("cp.async.commit_group;" ::: "memory")
#define CP_WAIT2()  asm volatile("cp.async.wait_group 2;" ::: "memory")
#define CP_WAIT1()  asm volatile("cp.async.wait_group 1;" ::: "memory")
#define CP_WAIT0()  asm volatile("cp.async.wait_group 0;" ::: "memory")

__device__ __forceinline__ void ldsm4(uint32_t r[4], uint32_t addr) {
    asm volatile("ldmatrix.sync.aligned.m8n8.x4.shared.b16 {%0,%1,%2,%3}, [%4];"
                 : "=r"(r[0]), "=r"(r[1]), "=r"(r[2]), "=r"(r[3]) : "r"(addr));
}

__device__ __forceinline__ void mma16816(float* d, const uint32_t* a,
                                         uint32_t b0, uint32_t b1) {
    asm volatile(
        "mma.sync.aligned.m16n8k16.row.col.f32.bf16.bf16.f32 "
        "{%0,%1,%2,%3}, {%4,%5,%6,%7}, {%8,%9}, {%0,%1,%2,%3};"
        : "+f"(d[0]), "+f"(d[1]), "+f"(d[2]), "+f"(d[3])
        : "r"(a[0]), "r"(a[1]), "r"(a[2]), "r"(a[3]), "r"(b0), "r"(b1));
}

__device__ __forceinline__ void split2(float a, float b,
                                       __nv_bfloat162& h, __nv_bfloat162& l2) {
    h = __float22bfloat162_rn(make_float2(a, b));
    float2 hf = __bfloat1622float2(h);
    l2 = __float22bfloat162_rn(make_float2(a - hf.x, b - hf.y));
}

// Copy one 128x64 bf16 tile (K-major) into SW128-swizzled smem
__device__ __forceinline__ void fill_copy(uint32_t dst,
                                          const __nv_bfloat16* __restrict__ src,
                                          size_t ld, int tid) {
    #pragma unroll
    for (int i = 0; i < 4; i++) {
        int s = tid + i * NT;
        int r = s >> 3, q = s & 7;
        cpa16(dst + SWZ((uint32_t)(r * 128 + q * 16)),
              src + (size_t)r * ld + q * 8);
    }
}

// bf16x3 MMA work for one 128x128 x K64 block.
// Stage layout: Ahi @0, Alo @16384, Bhi @32768, Blo @49152 (16KB each).
__device__ __forceinline__ void mma_k64(uint32_t base, uint32_t aoff,
                                        uint32_t boff, float (&acc)[2][8][4]) {
    #pragma unroll
    for (int c = 0; c < 4; c++) {
        uint32_t ao = 32u * c;
        uint32_t ahi[2][4], alo[2][4], bhi[4][4], blo[4][4];
        ldsm4(ahi[0], base +         SWZ(aoff + ao));
        ldsm4(ahi[1], base +         SWZ(aoff + 2048 + ao));
        ldsm4(alo[0], base + 16384 + SWZ(aoff + ao));
        ldsm4(alo[1], base + 16384 + SWZ(aoff + 2048 + ao));
        #pragma unroll
        for (int j = 0; j < 4; j++) {
            ldsm4(bhi[j], base + 32768 + SWZ(boff + j * 2048 + ao));
            ldsm4(blo[j], base + 49152 + SWZ(boff + j * 2048 + ao));
        }
        #pragma unroll
        for (int j = 0; j < 4; j++)
            #pragma unroll
            for (int mf = 0; mf < 2; mf++) {
                mma16816(acc[mf][2*j],     ahi[mf], bhi[j][0], bhi[j][1]);
                mma16816(acc[mf][2*j + 1], ahi[mf], bhi[j][2], bhi[j][3]);
            }
        #pragma unroll
        for (int j = 0; j < 4; j++)
            #pragma unroll
            for (int mf = 0; mf < 2; mf++) {
                mma16816(acc[mf][2*j],     ahi[mf], blo[j][0], blo[j][1]);
                mma16816(acc[mf][2*j + 1], ahi[mf], blo[j][2], blo[j][3]);
            }
        #pragma unroll
        for (int j = 0; j < 4; j++)
            #pragma unroll
            for (int mf = 0; mf < 2; mf++) {
                mma16816(acc[mf][2*j],     alo[mf], bhi[j][0], bhi[j][1]);
                mma16816(acc[mf][2*j + 1], alo[mf], bhi[j][2], bhi[j][3]);
            }
    }
}

// ---------------------------------------------------------------------------
// qkv: 2-stage non-persistent GEMM (R8 structure, staged epilogue for V^T)
// ---------------------------------------------------------------------------
__device__ __forceinline__ void gemm_main2(
    const __nv_bfloat16* __restrict__ Ah, const __nv_bfloat16* __restrict__ Al,
    const __nv_bfloat16* __restrict__ Bh, const __nv_bfloat16* __restrict__ Bl,
    size_t lda, size_t ldb, int nkb, uint32_t sbuf, float (&acc)[2][8][4])
{
    const int tid = threadIdx.x, l = tid & 31, wid = tid >> 5;
    const int mw = (wid >> 1) * 32, nw = (wid & 1) * 64;
    const uint32_t aoff = (uint32_t)((mw + (l & 15)) * 128 + ((l >> 4) & 1) * 16);
    const uint32_t boff = (uint32_t)((nw + (l & 7) + ((l >> 4) & 1) * 8) * 128 +
                                     ((l >> 3) & 1) * 16);

    fill_copy(sbuf,         Ah, lda, tid);
    fill_copy(sbuf + 16384, Al, lda, tid);
    fill_copy(sbuf + 32768, Bh, ldb, tid);
    fill_copy(sbuf + 49152, Bl, ldb, tid);
    CP_COMMIT();

    for (int kb = 0; kb < nkb; kb++) {
        if (kb + 1 < nkb) {
            uint32_t nbuf = sbuf + ((kb + 1) & 1) * STAGE2;
            size_t ko = (size_t)(kb + 1) * 64;
            fill_copy(nbuf,         Ah + ko, lda, tid);
            fill_copy(nbuf + 16384, Al + ko, lda, tid);
            fill_copy(nbuf + 32768, Bh + ko, ldb, tid);
            fill_copy(nbuf + 49152, Bl + ko, ldb, tid);
            CP_COMMIT();
            CP_WAIT1();
        } else {
            CP_WAIT0();
        }
        __syncthreads();
        mma_k64(sbuf + (kb & 1) * STAGE2, aoff, boff, acc);
        __syncthreads();
    }
}

__device__ __forceinline__ void store_stage(float* stage, float (&acc)[2][8][4]) {
    const int tid = threadIdx.x, l = tid & 31, wid = tid >> 5;
    const int mw = (wid >> 1) * 32, nw = (wid & 1) * 64;
    const int r0 = mw + (l >> 2), c0 = nw + (l & 3) * 2;
    #pragma unroll
    for (int mf = 0; mf < 2; mf++)
        #pragma unroll
        for (int nf = 0; nf < 8; nf++) {
            int cc = c0 + nf * 8;
            *(float2*)&stage[(r0 + mf * 16) * 132 + cc] =
                make_float2(acc[mf][nf][0], acc[mf][nf][1]);
            *(float2*)&stage[(r0 + mf * 16 + 8) * 132 + cc] =
                make_float2(acc[mf][nf][2], acc[mf][nf][3]);
        }
}

// ---------------------------------------------------------------------------
// Split fp32 -> (hi, lo) bf16. Region 0 = X, regions 1..3 = Wq/Wk/Wv.
// ---------------------------------------------------------------------------
__global__ __launch_bounds__(NT) void split_k(const float* __restrict__ X,
                                              const float* __restrict__ Wq,
                                              const float* __restrict__ Wk,
                                              const float* __restrict__ Wv,
                                              __nv_bfloat16* __restrict__ Xhi,
                                              __nv_bfloat16* __restrict__ Xlo,
                                              __nv_bfloat16* __restrict__ Whi,
                                              __nv_bfloat16* __restrict__ Wlo)
{
    const int nx = MTOT * E / 4;
    const int nw = H * E / 4;
    int i = blockIdx.x * NT + threadIdx.x;
    const float* src;
    __nv_bfloat16 *hi, *lo;
    int j;
    if (i < nx) {
        src = X; hi = Xhi; lo = Xlo; j = i;
    } else {
        int t = i - nx;
        int w = t / nw;
        j = t - w * nw;
        src = (w == 0) ? Wq : (w == 1) ? Wk : Wv;
        hi = Whi + (size_t)w * H * E;
        lo = Wlo + (size_t)w * H * E;
    }
    float4 v = ((const float4*)src)[j];
    __nv_bfloat162 h0, l0, h1, l1;
    split2(v.x, v.y, h0, l0);
    split2(v.z, v.w, h1, l1);
    ((__nv_bfloat162*)hi)[2 * j]     = h0;
    ((__nv_bfloat162*)hi)[2 * j + 1] = h1;
    ((__nv_bfloat162*)lo)[2 * j]     = l0;
    ((__nv_bfloat162*)lo)[2 * j + 1] = l1;
}

// ---------------------------------------------------------------------------
// QKV projection GEMM. grid (H/128, MTOT/128, 3)
// ---------------------------------------------------------------------------
__global__ __launch_bounds__(NT) void qkv_mm(const float* __restrict__ bq,
                                             const float* __restrict__ bk,
                                             const float* __restrict__ bv)
{
    extern __shared__ char dsm[];
    uint32_t sbuf = smem_u32(dsm);
    const int tid = threadIdx.x;
    const int z = blockIdx.z, row0 = blockIdx.y * 128, col0 = blockIdx.x * 128;

    const __nv_bfloat16* Ah = g_Xhi + (size_t)row0 * E;
    const __nv_bfloat16* Al = g_Xlo + (size_t)row0 * E;
    const __nv_bfloat16* Bh = g_Whi + ((size_t)z * H + col0) * E;
    const __nv_bfloat16* Bl = g_Wlo + ((size_t)z * H + col0) * E;

    float acc[2][8][4] = {};
    gemm_main2(Ah, Al, Bh, Bl, E, E, E / 64, sbuf, acc);

    float* stage = (float*)dsm;
    store_stage(stage, acc);
    __syncthreads();

    const float* bias = (z == 0) ? bq : (z == 1) ? bk : bv;

    if (z < 2) {
        __nv_bfloat16* ohi = (z == 0) ? g_Qhi : g_Khi;
        __nv_bfloat16* olo = (z == 0) ? g_Qlo : g_Klo;
        #pragma unroll
        for (int i = 0; i < 32; i++) {
            int s = tid + i * NT;          // 0..8191 pair slots
            int m = s >> 6, c2 = (s & 63) * 2;
            float a = stage[m * 132 + c2]     + __ldg(&bias[col0 + c2]);
            float b = stage[m * 132 + c2 + 1] + __ldg(&bias[col0 + c2 + 1]);
            __nv_bfloat162 h, l2;
            split2(a, b, h, l2);
            size_t idx = ((size_t)(row0 + m) * H + col0 + c2) >> 1;
            ((__nv_bfloat162*)ohi)[idx] = h;
            ((__nv_bfloat162*)olo)[idx] = l2;
        }
    } else {
        // V: write transposed [b][h][s]
        #pragma unroll
        for (int i = 0; i < 32; i++) {
            int p = tid + i * NT;          // 0..8191 pair slots
            int c = p >> 6, mp = (p & 63) * 2;
            float bs = __ldg(&bias[col0 + c]);
            float a = stage[mp * 132 + c] + bs;
            float b = stage[(mp + 1) * 132 + c] + bs;
            __nv_bfloat162 h, l2;
            split2(a, b, h, l2);
            size_t idx = (((size_t)(row0 >> 12) * H + col0 + c) * SQ +
                          (row0 & 4095) + mp) >> 1;
            ((__nv_bfloat162*)g_Vthi)[idx] = h;
            ((__nv_bfloat162*)g_Vtlo)[idx] = l2;
        }
    }
}

// ---------------------------------------------------------------------------
// Scores: persistent 3-stage streamed GEMM (R8 form) + zero `out` for pv's
// split-K atomics (stream order guarantees visibility before pv launches).
// ---------------------------------------------------------------------------
__global__ __launch_bounds__(NT) void scores_mm(const int* __restrict__ mask,
                                                float* __restrict__ outz)
{
    extern __shared__ char dsm[];
    uint32_t sbuf = smem_u32(dsm);
    const int tid = threadIdx.x, l = tid & 31, wid = tid >> 5;
    const int mw = (wid >> 1) * 32, nw = (wid & 1) * 64;
    const uint32_t aoff = (uint32_t)((mw + (l & 15)) * 128 + ((l >> 4) & 1) * 16);
    const uint32_t boff = (uint32_t)((nw + (l & 7) + ((l >> 4) & 1) * 8) * 128 +
                                     ((l >> 3) & 1) * 16);
    const int G = gridDim.x;
    const int NTILES = (SQ / 128) * (SQ / 128) * NB;   // 2048
    const int NKB = H / 64;                             // 16

    int t_f = blockIdx.x, kb_f = 0, fp = 0;

    auto fill_step = [&]() {
        if (t_f < NTILES) {
            int bz = t_f >> 10, rem = t_f & 1023;
            int row0 = (rem >> 5) << 7, col0 = (rem & 31) << 7;
            size_t ko = (size_t)kb_f * 64;
            uint32_t b = sbuf + (uint32_t)(fp % 3) * STAGE3;
            fill_copy(b,         g_Qhi + ((size_t)(bz * SQ + row0)) * H + ko, H, tid);
            fill_copy(b + 16384, g_Qlo + ((size_t)(bz * SQ + row0)) * H + ko, H, tid);
            fill_copy(b + 32768, g_Khi + ((size_t)(bz * SQ + col0)) * H + ko, H, tid);
            fill_copy(b + 49152, g_Klo + ((size_t)(bz * SQ + col0)) * H + ko, H, tid);
        }
        CP_COMMIT();
        fp++;
        if (++kb_f == NKB) { kb_f = 0; t_f += G; }
    };
    fill_step();
    fill_step();

    // Zero `out` for pv's atomic split-K reduction (33.5MB; hidden under
    // this MMA-bound kernel).
    {
        const int n4 = MTOT * H / 4;
        for (int i = blockIdx.x * NT + tid; i < n4; i += G * NT)
            ((float4*)outz)[i] = make_float4(0.f, 0.f, 0.f, 0.f);
    }

    float acc[2][8][4] = {};
    int cp = 0;
    const float scale = 0.03125f;  // 1/sqrt(1024)
    const int r0 = mw + (l >> 2), c0 = nw + (l & 3) * 2;

    for (int t = blockIdx.x; t < NTILES; t += G) {
        for (int kb = 0; kb < NKB; kb++) {
            fill_step();                 // group cp+2 into stage (cp+2)%3
            CP_WAIT2();                  // own groups <= cp complete
            __syncthreads();             // all threads' group cp visible
            mma_k64(sbuf + (uint32_t)(cp % 3) * STAGE3, aoff, boff, acc);
            __syncthreads();             // stage cp%3 free before refill
            cp++;
        }
        int bz = t >> 10, rem = t & 1023;
        int row0 = (rem >> 5) << 7, col0 = (rem & 31) << 7;
        const size_t pbase = (size_t)bz * SQ * SQ;
        #pragma unroll
        for (int mf = 0; mf < 2; mf++)
            #pragma unroll
            for (int nf = 0; nf < 8; nf++)
                #pragma unroll
                for (int hh = 0; hh < 2; hh++) {
                    int r = row0 + r0 + mf * 16 + hh * 8;
                    int c = col0 + c0 + nf * 8;
                    size_t gi = pbase + (size_t)r * SQ + c;
                    int2 mk = __ldg((const int2*)(mask + gi));
                    float2 v;
                    v.x = (mk.x == 0) ? -CUDART_INF_F : acc[mf][nf][hh*2]     * scale;
                    v.y = (mk.y == 0) ? -CUDART_INF_F : acc[mf][nf][hh*2 + 1] * scale;
                    *(float2*)(g_P + gi) = v;
                    acc[mf][nf][hh*2] = 0.0f;
                    acc[mf][nf][hh*2 + 1] = 0.0f;
                }
    }
}

// ---------------------------------------------------------------------------
// Row softmax of g_P -> split bf16 P. One block per row; row in registers.
// ---------------------------------------------------------------------------
__global__ __launch_bounds__(256) void softmax_k()
{
    __shared__ float red[8];
    const int tid = threadIdx.x;
    const float* p = g_P + (size_t)blockIdx.x * SQ;

    float4 v[4];
    float m = -CUDART_INF_F;
    #pragma unroll
    for (int i = 0; i < 4; i++) {
        v[i] = __ldg((const float4*)(p + (size_t)(i * 256 + tid) * 4));
        m = fmaxf(m, fmaxf(fmaxf(v[i].x, v[i].y), fmaxf(v[i].z, v[i].w)));
    }
    #pragma unroll
    for (int o = 16; o; o >>= 1) m = fmaxf(m, __shfl_xor_sync(0xFFFFFFFFu, m, o));
    if ((tid & 31) == 0) red[tid >> 5] = m;
    __syncthreads();
    m = fmaxf(fmaxf(fmaxf(red[0], red[1]), fmaxf(red[2], red[3])),
              fmaxf(fmaxf(red[4], red[5]), fmaxf(red[6], red[7])));
    __syncthreads();

    float s = 0.0f;
    #pragma unroll
    for (int i = 0; i < 4; i++) {
        v[i].x = __expf(v[i].x - m); v[i].y = __expf(v[i].y - m);
        v[i].z = __expf(v[i].z - m); v[i].w = __expf(v[i].w - m);
        s += (v[i].x + v[i].y) + (v[i].z + v[i].w);
    }
    #pragma unroll
    for (int o = 16; o; o >>= 1) s += __shfl_xor_sync(0xFFFFFFFFu, s, o);
    if ((tid & 31) == 0) red[tid >> 5] = s;
    __syncthreads();
    s = ((red[0] + red[1]) + (red[2] + red[3])) +
        ((red[4] + red[5]) + (red[6] + red[7]));
    float inv = 1.0f / s;

    size_t r2 = (size_t)blockIdx.x * (SQ / 2);
    #pragma unroll
    for (int i = 0; i < 4; i++) {
        int base = (i * 256 + tid) * 2;
        __nv_bfloat162 h0, l0, h1, l1;
        split2(v[i].x * inv, v[i].y * inv, h0, l0);
        split2(v[i].z * inv, v[i].w * inv, h1, l1);
        ((__nv_bfloat162*)g_Phi)[r2 + base]     = h0;
        ((__nv_bfloat162*)g_Phi)[r2 + base + 1] = h1;
        ((__nv_bfloat162*)g_Plo)[r2 + base]     = l0;
        ((__nv_bfloat162*)g_Plo)[r2 + base + 1] = l1;
    }
}

// ---------------------------------------------------------------------------
// PV: persistent 3-stage streamed GEMM with SPLIT-K-2.
// 1024 work units u = (tile t = u>>1, khalf = u&1); each unit K=2048
// (32 k-blocks). 1024/G waves eliminate the 512/148 tail (4.0T -> 3.5T).
// Reduction: fp32 atomicAdd into pre-zeroed `out` (commutative -> exact).
// ---------------------------------------------------------------------------
__global__ __launch_bounds__(NT) void pv_mm(float* __restrict__ out)
{
    extern __shared__ char dsm[];
    uint32_t sbuf = smem_u32(dsm);
    const int tid = threadIdx.x, l = tid & 31, wid = tid >> 5;
    const int mw = (wid >> 1) * 32, nw = (wid & 1) * 64;
    const uint32_t aoff = (uint32_t)((mw + (l & 15)) * 128 + ((l >> 4) & 1) * 16);
    const uint32_t boff = (uint32_t)((nw + (l & 7) + ((l >> 4) & 1) * 8) * 128 +
                                     ((l >> 3) & 1) * 16);
    const int G = gridDim.x;
    const int NUNITS = (H / 128) * (SQ / 128) * NB * 2;  // 1024
    const int NKB = SQ / 128;                             // 32 k-blocks per unit

    int t_f = blockIdx.x, kb_f = 0, fp = 0;

    auto fill_step = [&]() {
        if (t_f < NUNITS) {
            int tt = t_f >> 1, kh = t_f & 1;
            int bz = tt >> 8, rem = tt & 255;
            int row0 = (rem >> 3) << 7, col0 = (rem & 7) << 7;
            size_t ko = (size_t)(kh * NKB + kb_f) * 64;
            uint32_t b = sbuf + (uint32_t)(fp % 3) * STAGE3;
            fill_copy(b,         g_Phi + (size_t)bz * SQ * SQ +
                                 (size_t)row0 * SQ + ko, SQ, tid);
            fill_copy(b + 16384, g_Plo + (size_t)bz * SQ * SQ +
                                 (size_t)row0 * SQ + ko, SQ, tid);
            fill_copy(b + 32768, g_Vthi + ((size_t)bz * H + col0) * SQ + ko, SQ, tid);
            fill_copy(b + 49152, g_Vtlo + ((size_t)bz * H + col0) * SQ + ko, SQ, tid);
        }
        CP_COMMIT();
        fp++;
        if (++kb_f == NKB) { kb_f = 0; t_f += G; }
    };
    fill_step();
    fill_step();

    float acc[2][8][4] = {};
    int cp = 0;
    const int r0 = mw + (l >> 2), c0 = nw + (l & 3) * 2;

    for (int u = blockIdx.x; u < NUNITS; u += G) {
        for (int kb = 0; kb < NKB; kb++) {
            fill_step();
            CP_WAIT2();
            __syncthreads();
            mma_k64(sbuf + (uint32_t)(cp % 3) * STAGE3, aoff, boff, acc);
            __syncthreads();
            cp++;
        }
        int tt = u >> 1;
        int bz = tt >> 8, rem = tt & 255;
        int row0 = (rem >> 3) << 7, col0 = (rem & 7) << 7;
        #pragma unroll
        for (int mf = 0; mf < 2; mf++)
            #pragma unroll
            for (int nf = 0; nf < 8; nf++)
                #pragma unroll
                for (int hh = 0; hh < 2; hh++) {
                    int r = row0 + r0 + mf * 16 + hh * 8;
                    int c = col0 + c0 + nf * 8;
                    float* o = &out[((size_t)bz * SQ + r) * H + c];
                    atomicAdd(o,     acc[mf][nf][hh*2]);
                    atomicAdd(o + 1, acc[mf][nf][hh*2 + 1]);
                    acc[mf][nf][hh*2] = 0.0f;
                    acc[mf][nf][hh*2 + 1] = 0.0f;
                }
    }
}

// ---------------------------------------------------------------------------
extern "C" void kernel_launch(void* const* d_in, const int* in_sizes, int n_in,
                              void* d_out, int out_size)
{
    const float* X    = (const float*)d_in[0];
    const int*   mask = (const int*)  d_in[1];
    const float* Wq   = (const float*)d_in[2];
    const float* bq   = (const float*)d_in[3];
    const float* Wk   = (const float*)d_in[4];
    const float* bk   = (const float*)d_in[5];
    const float* Wv   = (const float*)d_in[6];
    const float* bv   = (const float*)d_in[7];
    float* out = (float*)d_out;

    cudaFuncSetAttribute(qkv_mm,    cudaFuncAttributeMaxDynamicSharedMemorySize, SMEM_QKV);
    cudaFuncSetAttribute(scores_mm, cudaFuncAttributeMaxDynamicSharedMemorySize, SMEM_S3);
    cudaFuncSetAttribute(pv_mm,     cudaFuncAttributeMaxDynamicSharedMemorySize, SMEM_S3);

    int dev = 0, nsm = 148;
    cudaGetDevice(&dev);
    cudaDeviceGetAttribute(&nsm, cudaDevAttrMultiProcessorCount, dev);

    __nv_bfloat16 *pXhi, *pXlo, *pWhi, *pWlo;
    cudaGetSymbolAddress((void**)&pXhi, g_Xhi);
    cudaGetSymbolAddress((void**)&pXlo, g_Xlo);
    cudaGetSymbolAddress((void**)&pWhi, g_Whi);
    cudaGetSymbolAddress((void**)&pWlo, g_Wlo);

    int total4 = (MTOT * E + 3 * H * E) / 4;
    split_k<<<total4 / NT, NT>>>(X, Wq, Wk, Wv, pXhi, pXlo, pWhi, pWlo);

    qkv_mm<<<dim3(H / 128, MTOT / 128, 3), NT, SMEM_QKV>>>(bq, bk, bv);
    scores_mm<<<nsm, NT, SMEM_S3>>>(mask, out);
    softmax_k<<<NB * SQ, 256>>>();
    pv_mm<<<nsm, NT, SMEM_S3>>>(out);
}

// round 15
// speedup vs baseline: 1.2995x; 1.2426x over previous
#include <cuda_runtime.h>
#include <cuda_bf16.h>
#include <cuda_fp16.h>
#include <cstdint>
#include <math_constants.h>

#define E    1024
#define H    1024
#define SQ   4096
#define NB   2
#define MTOT 8192
#define NT   256
#define STAGE2    65536     // 2-stage buffer size (qkv)
#define SMEM_QKV  131072
#define STAGE3    65536     // per-stage size, scores
#define SMEM_S3   196608
#define STAGE_PV  32768     // pv: A f16 16KB + B f16 16KB
#define SMEM_PV   98304

// ---------------------------------------------------------------------------
// Device scratch (allocation-free per harness rules)
// ---------------------------------------------------------------------------
__device__ __align__(256) __nv_bfloat16 g_Xhi[(size_t)MTOT * E];
__device__ __align__(256) __nv_bfloat16 g_Xlo[(size_t)MTOT * E];
__device__ __align__(256) __nv_bfloat16 g_Whi[(size_t)3 * H * E];
__device__ __align__(256) __nv_bfloat16 g_Wlo[(size_t)3 * H * E];
__device__ __align__(256) __nv_bfloat16 g_Qhi[(size_t)MTOT * H];
__device__ __align__(256) __nv_bfloat16 g_Qlo[(size_t)MTOT * H];
__device__ __align__(256) __nv_bfloat16 g_Khi[(size_t)MTOT * H];
__device__ __align__(256) __nv_bfloat16 g_Klo[(size_t)MTOT * H];
__device__ __align__(256) __half        g_Vt16[(size_t)NB * H * SQ]; // [b][h][s] fp16
__device__ __align__(256) float         g_P  [(size_t)NB * SQ * SQ];
__device__ __align__(256) __half        g_P16[(size_t)NB * SQ * SQ]; // fp16 softmax out

// ---------------------------------------------------------------------------
// Helpers
// ---------------------------------------------------------------------------
__device__ __forceinline__ uint32_t smem_u32(const void* p) {
    uint32_t a;
    asm("{ .reg .u64 t; cvta.to.shared.u64 t, %1; cvt.u32.u64 %0, t; }"
        : "=r"(a) : "l"(p));
    return a;
}

#define SWZ(o) ((o) ^ (((o) >> 3) & 0x70))

__device__ __forceinline__ void cpa16(uint32_t dst, const void* src) {
    asm volatile("cp.async.cg.shared.global [%0], [%1], 16;" :: "r"(dst), "l"(src));
}
#define CP_COMMIT() asm volatile("cp.async.commit_group;" ::: "memory")
#define CP_WAIT2()  asm volatile("cp.async.wait_group 2;" ::: "memory")
#define CP_WAIT1()  asm volatile("cp.async.wait_group 1;" ::: "memory")
#define CP_WAIT0()  asm volatile("cp.async.wait_group 0;" ::: "memory")

__device__ __forceinline__ void ldsm4(uint32_t r[4], uint32_t addr) {
    asm volatile("ldmatrix.sync.aligned.m8n8.x4.shared.b16 {%0,%1,%2,%3}, [%4];"
                 : "=r"(r[0]), "=r"(r[1]), "=r"(r[2]), "=r"(r[3]) : "r"(addr));
}

__device__ __forceinline__ void mma16816(float* d, const uint32_t* a,
                                         uint32_t b0, uint32_t b1) {
    asm volatile(
        "mma.sync.aligned.m16n8k16.row.col.f32.bf16.bf16.f32 "
        "{%0,%1,%2,%3}, {%4,%5,%6,%7}, {%8,%9}, {%0,%1,%2,%3};"
        : "+f"(d[0]), "+f"(d[1]), "+f"(d[2]), "+f"(d[3])
        : "r"(a[0]), "r"(a[1]), "r"(a[2]), "r"(a[3]), "r"(b0), "r"(b1));
}

__device__ __forceinline__ void mma16816h(float* d, const uint32_t* a,
                                          uint32_t b0, uint32_t b1) {
    asm volatile(
        "mma.sync.aligned.m16n8k16.row.col.f32.f16.f16.f32 "
        "{%0,%1,%2,%3}, {%4,%5,%6,%7}, {%8,%9}, {%0,%1,%2,%3};"
        : "+f"(d[0]), "+f"(d[1]), "+f"(d[2]), "+f"(d[3])
        : "r"(a[0]), "r"(a[1]), "r"(a[2]), "r"(a[3]), "r"(b0), "r"(b1));
}

__device__ __forceinline__ void split2(float a, float b,
                                       __nv_bfloat162& h, __nv_bfloat162& l2) {
    h = __float22bfloat162_rn(make_float2(a, b));
    float2 hf = __bfloat1622float2(h);
    l2 = __float22bfloat162_rn(make_float2(a - hf.x, b - hf.y));
}

// Copy one 128x64 16-bit-elem tile (K-major) into SW128-swizzled smem
__device__ __forceinline__ void fill_copy(uint32_t dst, const void* __restrict__ srcv,
                                          size_t ld, int tid) {
    const __nv_bfloat16* src = (const __nv_bfloat16*)srcv;
    #pragma unroll
    for (int i = 0; i < 4; i++) {
        int s = tid + i * NT;
        int r = s >> 3, q = s & 7;
        cpa16(dst + SWZ((uint32_t)(r * 128 + q * 16)),
              src + (size_t)r * ld + q * 8);
    }
}

// bf16x3 MMA work for one 128x128 x K64 block.
// Stage layout: Ahi @0, Alo @16384, Bhi @32768, Blo @49152 (16KB each).
__device__ __forceinline__ void mma_k64(uint32_t base, uint32_t aoff,
                                        uint32_t boff, float (&acc)[2][8][4]) {
    #pragma unroll
    for (int c = 0; c < 4; c++) {
        uint32_t ao = 32u * c;
        uint32_t ahi[2][4], alo[2][4], bhi[4][4], blo[4][4];
        ldsm4(ahi[0], base +         SWZ(aoff + ao));
        ldsm4(ahi[1], base +         SWZ(aoff + 2048 + ao));
        ldsm4(alo[0], base + 16384 + SWZ(aoff + ao));
        ldsm4(alo[1], base + 16384 + SWZ(aoff + 2048 + ao));
        #pragma unroll
        for (int j = 0; j < 4; j++) {
            ldsm4(bhi[j], base + 32768 + SWZ(boff + j * 2048 + ao));
            ldsm4(blo[j], base + 49152 + SWZ(boff + j * 2048 + ao));
        }
        #pragma unroll
        for (int j = 0; j < 4; j++)
            #pragma unroll
            for (int mf = 0; mf < 2; mf++) {
                mma16816(acc[mf][2*j],     ahi[mf], bhi[j][0], bhi[j][1]);
                mma16816(acc[mf][2*j + 1], ahi[mf], bhi[j][2], bhi[j][3]);
            }
        #pragma unroll
        for (int j = 0; j < 4; j++)
            #pragma unroll
            for (int mf = 0; mf < 2; mf++) {
                mma16816(acc[mf][2*j],     ahi[mf], blo[j][0], blo[j][1]);
                mma16816(acc[mf][2*j + 1], ahi[mf], blo[j][2], blo[j][3]);
            }
        #pragma unroll
        for (int j = 0; j < 4; j++)
            #pragma unroll
            for (int mf = 0; mf < 2; mf++) {
                mma16816(acc[mf][2*j],     alo[mf], bhi[j][0], bhi[j][1]);
                mma16816(acc[mf][2*j + 1], alo[mf], bhi[j][2], bhi[j][3]);
            }
    }
}

// Single-term fp16 MMA for one 128x128 x K64 block (pv).
// Stage layout: A(f16) @0 (16KB), B(f16) @16384.
__device__ __forceinline__ void mma_k64_f16(uint32_t base, uint32_t aoff,
                                            uint32_t boff, float (&acc)[2][8][4]) {
    #pragma unroll
    for (int c = 0; c < 4; c++) {
        uint32_t ao = 32u * c;
        uint32_t ah[2][4], bh[4][4];
        ldsm4(ah[0], base + SWZ(aoff + ao));
        ldsm4(ah[1], base + SWZ(aoff + 2048 + ao));
        #pragma unroll
        for (int j = 0; j < 4; j++)
            ldsm4(bh[j], base + 16384 + SWZ(boff + j * 2048 + ao));
        #pragma unroll
        for (int j = 0; j < 4; j++)
            #pragma unroll
            for (int mf = 0; mf < 2; mf++) {
                mma16816h(acc[mf][2*j],     ah[mf], bh[j][0], bh[j][1]);
                mma16816h(acc[mf][2*j + 1], ah[mf], bh[j][2], bh[j][3]);
            }
    }
}

// ---------------------------------------------------------------------------
// qkv: 2-stage non-persistent GEMM (R8 structure, staged epilogue for V^T)
// ---------------------------------------------------------------------------
__device__ __forceinline__ void gemm_main2(
    const __nv_bfloat16* __restrict__ Ah, const __nv_bfloat16* __restrict__ Al,
    const __nv_bfloat16* __restrict__ Bh, const __nv_bfloat16* __restrict__ Bl,
    size_t lda, size_t ldb, int nkb, uint32_t sbuf, float (&acc)[2][8][4])
{
    const int tid = threadIdx.x, l = tid & 31, wid = tid >> 5;
    const int mw = (wid >> 1) * 32, nw = (wid & 1) * 64;
    const uint32_t aoff = (uint32_t)((mw + (l & 15)) * 128 + ((l >> 4) & 1) * 16);
    const uint32_t boff = (uint32_t)((nw + (l & 7) + ((l >> 4) & 1) * 8) * 128 +
                                     ((l >> 3) & 1) * 16);

    fill_copy(sbuf,         Ah, lda, tid);
    fill_copy(sbuf + 16384, Al, lda, tid);
    fill_copy(sbuf + 32768, Bh, ldb, tid);
    fill_copy(sbuf + 49152, Bl, ldb, tid);
    CP_COMMIT();

    for (int kb = 0; kb < nkb; kb++) {
        if (kb + 1 < nkb) {
            uint32_t nbuf = sbuf + ((kb + 1) & 1) * STAGE2;
            size_t ko = (size_t)(kb + 1) * 64;
            fill_copy(nbuf,         Ah + ko, lda, tid);
            fill_copy(nbuf + 16384, Al + ko, lda, tid);
            fill_copy(nbuf + 32768, Bh + ko, ldb, tid);
            fill_copy(nbuf + 49152, Bl + ko, ldb, tid);
            CP_COMMIT();
            CP_WAIT1();
        } else {
            CP_WAIT0();
        }
        __syncthreads();
        mma_k64(sbuf + (kb & 1) * STAGE2, aoff, boff, acc);
        __syncthreads();
    }
}

__device__ __forceinline__ void store_stage(float* stage, float (&acc)[2][8][4]) {
    const int tid = threadIdx.x, l = tid & 31, wid = tid >> 5;
    const int mw = (wid >> 1) * 32, nw = (wid & 1) * 64;
    const int r0 = mw + (l >> 2), c0 = nw + (l & 3) * 2;
    #pragma unroll
    for (int mf = 0; mf < 2; mf++)
        #pragma unroll
        for (int nf = 0; nf < 8; nf++) {
            int cc = c0 + nf * 8;
            *(float2*)&stage[(r0 + mf * 16) * 132 + cc] =
                make_float2(acc[mf][nf][0], acc[mf][nf][1]);
            *(float2*)&stage[(r0 + mf * 16 + 8) * 132 + cc] =
                make_float2(acc[mf][nf][2], acc[mf][nf][3]);
        }
}

// ---------------------------------------------------------------------------
// Split fp32 -> (hi, lo) bf16. Region 0 = X, regions 1..3 = Wq/Wk/Wv.
// ---------------------------------------------------------------------------
__global__ __launch_bounds__(NT) void split_k(const float* __restrict__ X,
                                              const float* __restrict__ Wq,
                                              const float* __restrict__ Wk,
                                              const float* __restrict__ Wv,
                                              __nv_bfloat16* __restrict__ Xhi,
                                              __nv_bfloat16* __restrict__ Xlo,
                                              __nv_bfloat16* __restrict__ Whi,
                                              __nv_bfloat16* __restrict__ Wlo)
{
    const int nx = MTOT * E / 4;
    const int nw = H * E / 4;
    int i = blockIdx.x * NT + threadIdx.x;
    const float* src;
    __nv_bfloat16 *hi, *lo;
    int j;
    if (i < nx) {
        src = X; hi = Xhi; lo = Xlo; j = i;
    } else {
        int t = i - nx;
        int w = t / nw;
        j = t - w * nw;
        src = (w == 0) ? Wq : (w == 1) ? Wk : Wv;
        hi = Whi + (size_t)w * H * E;
        lo = Wlo + (size_t)w * H * E;
    }
    float4 v = ((const float4*)src)[j];
    __nv_bfloat162 h0, l0, h1, l1;
    split2(v.x, v.y, h0, l0);
    split2(v.z, v.w, h1, l1);
    ((__nv_bfloat162*)hi)[2 * j]     = h0;
    ((__nv_bfloat162*)hi)[2 * j + 1] = h1;
    ((__nv_bfloat162*)lo)[2 * j]     = l0;
    ((__nv_bfloat162*)lo)[2 * j + 1] = l1;
}

// ---------------------------------------------------------------------------
// QKV projection GEMM. grid (H/128, MTOT/128, 3)
// ---------------------------------------------------------------------------
__global__ __launch_bounds__(NT) void qkv_mm(const float* __restrict__ bq,
                                             const float* __restrict__ bk,
                                             const float* __restrict__ bv)
{
    extern __shared__ char dsm[];
    uint32_t sbuf = smem_u32(dsm);
    const int tid = threadIdx.x;
    const int z = blockIdx.z, row0 = blockIdx.y * 128, col0 = blockIdx.x * 128;

    const __nv_bfloat16* Ah = g_Xhi + (size_t)row0 * E;
    const __nv_bfloat16* Al = g_Xlo + (size_t)row0 * E;
    const __nv_bfloat16* Bh = g_Whi + ((size_t)z * H + col0) * E;
    const __nv_bfloat16* Bl = g_Wlo + ((size_t)z * H + col0) * E;

    float acc[2][8][4] = {};
    gemm_main2(Ah, Al, Bh, Bl, E, E, E / 64, sbuf, acc);

    float* stage = (float*)dsm;
    store_stage(stage, acc);
    __syncthreads();

    const float* bias = (z == 0) ? bq : (z == 1) ? bk : bv;

    if (z < 2) {
        __nv_bfloat16* ohi = (z == 0) ? g_Qhi : g_Khi;
        __nv_bfloat16* olo = (z == 0) ? g_Qlo : g_Klo;
        #pragma unroll
        for (int i = 0; i < 32; i++) {
            int s = tid + i * NT;          // 0..8191 pair slots
            int m = s >> 6, c2 = (s & 63) * 2;
            float a = stage[m * 132 + c2]     + __ldg(&bias[col0 + c2]);
            float b = stage[m * 132 + c2 + 1] + __ldg(&bias[col0 + c2 + 1]);
            __nv_bfloat162 h, l2;
            split2(a, b, h, l2);
            size_t idx = ((size_t)(row0 + m) * H + col0 + c2) >> 1;
            ((__nv_bfloat162*)ohi)[idx] = h;
            ((__nv_bfloat162*)olo)[idx] = l2;
        }
    } else {
        // V: write transposed [b][h][s], single fp16
        #pragma unroll
        for (int i = 0; i < 32; i++) {
            int p = tid + i * NT;          // 0..8191 pair slots
            int c = p >> 6, mp = (p & 63) * 2;
            float bs = __ldg(&bias[col0 + c]);
            float a = stage[mp * 132 + c] + bs;
            float b = stage[(mp + 1) * 132 + c] + bs;
            size_t idx = (((size_t)(row0 >> 12) * H + col0 + c) * SQ +
                          (row0 & 4095) + mp) >> 1;
            ((__half2*)g_Vt16)[idx] = __floats2half2_rn(a, b);
        }
    }
}

// ---------------------------------------------------------------------------
// Scores: persistent 3-stage streamed GEMM (R8 form) + zero `out` for pv's
// split-K atomics (stream order guarantees visibility before pv launches).
// ---------------------------------------------------------------------------
__global__ __launch_bounds__(NT) void scores_mm(const int* __restrict__ mask,
                                                float* __restrict__ outz)
{
    extern __shared__ char dsm[];
    uint32_t sbuf = smem_u32(dsm);
    const int tid = threadIdx.x, l = tid & 31, wid = tid >> 5;
    const int mw = (wid >> 1) * 32, nw = (wid & 1) * 64;
    const uint32_t aoff = (uint32_t)((mw + (l & 15)) * 128 + ((l >> 4) & 1) * 16);
    const uint32_t boff = (uint32_t)((nw + (l & 7) + ((l >> 4) & 1) * 8) * 128 +
                                     ((l >> 3) & 1) * 16);
    const int G = gridDim.x;
    const int NTILES = (SQ / 128) * (SQ / 128) * NB;   // 2048
    const int NKB = H / 64;                             // 16

    int t_f = blockIdx.x, kb_f = 0, fp = 0;

    auto fill_step = [&]() {
        if (t_f < NTILES) {
            int bz = t_f >> 10, rem = t_f & 1023;
            int row0 = (rem >> 5) << 7, col0 = (rem & 31) << 7;
            size_t ko = (size_t)kb_f * 64;
            uint32_t b = sbuf + (uint32_t)(fp % 3) * STAGE3;
            fill_copy(b,         g_Qhi + ((size_t)(bz * SQ + row0)) * H + ko, H, tid);
            fill_copy(b + 16384, g_Qlo + ((size_t)(bz * SQ + row0)) * H + ko, H, tid);
            fill_copy(b + 32768, g_Khi + ((size_t)(bz * SQ + col0)) * H + ko, H, tid);
            fill_copy(b + 49152, g_Klo + ((size_t)(bz * SQ + col0)) * H + ko, H, tid);
        }
        CP_COMMIT();
        fp++;
        if (++kb_f == NKB) { kb_f = 0; t_f += G; }
    };
    fill_step();
    fill_step();

    // Zero `out` for pv's atomic split-K reduction (hidden under MMA).
    {
        const int n4 = MTOT * H / 4;
        for (int i = blockIdx.x * NT + tid; i < n4; i += G * NT)
            ((float4*)outz)[i] = make_float4(0.f, 0.f, 0.f, 0.f);
    }

    float acc[2][8][4] = {};
    int cp = 0;
    const float scale = 0.03125f;  // 1/sqrt(1024)
    const int r0 = mw + (l >> 2), c0 = nw + (l & 3) * 2;

    for (int t = blockIdx.x; t < NTILES; t += G) {
        for (int kb = 0; kb < NKB; kb++) {
            fill_step();
            CP_WAIT2();
            __syncthreads();
            mma_k64(sbuf + (uint32_t)(cp % 3) * STAGE3, aoff, boff, acc);
            __syncthreads();
            cp++;
        }
        int bz = t >> 10, rem = t & 1023;
        int row0 = (rem >> 5) << 7, col0 = (rem & 31) << 7;
        const size_t pbase = (size_t)bz * SQ * SQ;
        #pragma unroll
        for (int mf = 0; mf < 2; mf++)
            #pragma unroll
            for (int nf = 0; nf < 8; nf++)
                #pragma unroll
                for (int hh = 0; hh < 2; hh++) {
                    int r = row0 + r0 + mf * 16 + hh * 8;
                    int c = col0 + c0 + nf * 8;
                    size_t gi = pbase + (size_t)r * SQ + c;
                    int2 mk = __ldg((const int2*)(mask + gi));
                    float2 v;
                    v.x = (mk.x == 0) ? -CUDART_INF_F : acc[mf][nf][hh*2]     * scale;
                    v.y = (mk.y == 0) ? -CUDART_INF_F : acc[mf][nf][hh*2 + 1] * scale;
                    *(float2*)(g_P + gi) = v;
                    acc[mf][nf][hh*2] = 0.0f;
                    acc[mf][nf][hh*2 + 1] = 0.0f;
                }
    }
}

// ---------------------------------------------------------------------------
// Row softmax of g_P -> fp16 P. One block per row; row in registers.
// ---------------------------------------------------------------------------
__global__ __launch_bounds__(256) void softmax_k()
{
    __shared__ float red[8];
    const int tid = threadIdx.x;
    const float* p = g_P + (size_t)blockIdx.x * SQ;

    float4 v[4];
    float m = -CUDART_INF_F;
    #pragma unroll
    for (int i = 0; i < 4; i++) {
        v[i] = __ldg((const float4*)(p + (size_t)(i * 256 + tid) * 4));
        m = fmaxf(m, fmaxf(fmaxf(v[i].x, v[i].y), fmaxf(v[i].z, v[i].w)));
    }
    #pragma unroll
    for (int o = 16; o; o >>= 1) m = fmaxf(m, __shfl_xor_sync(0xFFFFFFFFu, m, o));
    if ((tid & 31) == 0) red[tid >> 5] = m;
    __syncthreads();
    m = fmaxf(fmaxf(fmaxf(red[0], red[1]), fmaxf(red[2], red[3])),
              fmaxf(fmaxf(red[4], red[5]), fmaxf(red[6], red[7])));
    __syncthreads();

    float s = 0.0f;
    #pragma unroll
    for (int i = 0; i < 4; i++) {
        v[i].x = __expf(v[i].x - m); v[i].y = __expf(v[i].y - m);
        v[i].z = __expf(v[i].z - m); v[i].w = __expf(v[i].w - m);
        s += (v[i].x + v[i].y) + (v[i].z + v[i].w);
    }
    #pragma unroll
    for (int o = 16; o; o >>= 1) s += __shfl_xor_sync(0xFFFFFFFFu, s, o);
    if ((tid & 31) == 0) red[tid >> 5] = s;
    __syncthreads();
    s = ((red[0] + red[1]) + (red[2] + red[3])) +
        ((red[4] + red[5]) + (red[6] + red[7]));
    float inv = 1.0f / s;

    size_t r2 = (size_t)blockIdx.x * (SQ / 2);
    #pragma unroll
    for (int i = 0; i < 4; i++) {
        int base = (i * 256 + tid) * 2;
        ((__half2*)g_P16)[r2 + base]     = __floats2half2_rn(v[i].x * inv, v[i].y * inv);
        ((__half2*)g_P16)[r2 + base + 1] = __floats2half2_rn(v[i].z * inv, v[i].w * inv);
    }
}

// ---------------------------------------------------------------------------
// PV: persistent 3-stage streamed fp16 GEMM with SPLIT-K-2.
// Single-term P(f16) x V(f16), fp32 accum. Atomic reduction into `out`.
// ---------------------------------------------------------------------------
__global__ __launch_bounds__(NT) void pv_mm(float* __restrict__ out)
{
    extern __shared__ char dsm[];
    uint32_t sbuf = smem_u32(dsm);
    const int tid = threadIdx.x, l = tid & 31, wid = tid >> 5;
    const int mw = (wid >> 1) * 32, nw = (wid & 1) * 64;
    const uint32_t aoff = (uint32_t)((mw + (l & 15)) * 128 + ((l >> 4) & 1) * 16);
    const uint32_t boff = (uint32_t)((nw + (l & 7) + ((l >> 4) & 1) * 8) * 128 +
                                     ((l >> 3) & 1) * 16);
    const int G = gridDim.x;
    const int NUNITS = (H / 128) * (SQ / 128) * NB * 2;  // 1024
    const int NKB = SQ / 128;                             // 32 k-blocks per unit

    int t_f = blockIdx.x, kb_f = 0, fp = 0;

    auto fill_step = [&]() {
        if (t_f < NUNITS) {
            int tt = t_f >> 1, kh = t_f & 1;
            int bz = tt >> 8, rem = tt & 255;
            int row0 = (rem >> 3) << 7, col0 = (rem & 7) << 7;
            size_t ko = (size_t)(kh * NKB + kb_f) * 64;
            uint32_t b = sbuf + (uint32_t)(fp % 3) * STAGE_PV;
            fill_copy(b,         g_P16  + (size_t)bz * SQ * SQ +
                                 (size_t)row0 * SQ + ko, SQ, tid);
            fill_copy(b + 16384, g_Vt16 + ((size_t)bz * H + col0) * SQ + ko, SQ, tid);
        }
        CP_COMMIT();
        fp++;
        if (++kb_f == NKB) { kb_f = 0; t_f += G; }
    };
    fill_step();
    fill_step();

    float acc[2][8][4] = {};
    int cp = 0;
    const int r0 = mw + (l >> 2), c0 = nw + (l & 3) * 2;

    for (int u = blockIdx.x; u < NUNITS; u += G) {
        for (int kb = 0; kb < NKB; kb++) {
            fill_step();
            CP_WAIT2();
            __syncthreads();
            mma_k64_f16(sbuf + (uint32_t)(cp % 3) * STAGE_PV, aoff, boff, acc);
            __syncthreads();
            cp++;
        }
        int tt = u >> 1;
        int bz = tt >> 8, rem = tt & 255;
        int row0 = (rem >> 3) << 7, col0 = (rem & 7) << 7;
        #pragma unroll
        for (int mf = 0; mf < 2; mf++)
            #pragma unroll
            for (int nf = 0; nf < 8; nf++)
                #pragma unroll
                for (int hh = 0; hh < 2; hh++) {
                    int r = row0 + r0 + mf * 16 + hh * 8;
                    int c = col0 + c0 + nf * 8;
                    float* o = &out[((size_t)bz * SQ + r) * H + c];
                    atomicAdd(o,     acc[mf][nf][hh*2]);
                    atomicAdd(o + 1, acc[mf][nf][hh*2 + 1]);
                    acc[mf][nf][hh*2] = 0.0f;
                    acc[mf][nf][hh*2 + 1] = 0.0f;
                }
    }
}

// ---------------------------------------------------------------------------
extern "C" void kernel_launch(void* const* d_in, const int* in_sizes, int n_in,
                              void* d_out, int out_size)
{
    const float* X    = (const float*)d_in[0];
    const int*   mask = (const int*)  d_in[1];
    const float* Wq   = (const float*)d_in[2];
    const float* bq   = (const float*)d_in[3];
    const float* Wk   = (const float*)d_in[4];
    const float* bk   = (const float*)d_in[5];
    const float* Wv   = (const float*)d_in[6];
    const float* bv   = (const float*)d_in[7];
    float* out = (float*)d_out;

    cudaFuncSetAttribute(qkv_mm,    cudaFuncAttributeMaxDynamicSharedMemorySize, SMEM_QKV);
    cudaFuncSetAttribute(scores_mm, cudaFuncAttributeMaxDynamicSharedMemorySize, SMEM_S3);
    cudaFuncSetAttribute(pv_mm,     cudaFuncAttributeMaxDynamicSharedMemorySize, SMEM_PV);

    int dev = 0, nsm = 148;
    cudaGetDevice(&dev);
    cudaDeviceGetAttribute(&nsm, cudaDevAttrMultiProcessorCount, dev);

    __nv_bfloat16 *pXhi, *pXlo, *pWhi, *pWlo;
    cudaGetSymbolAddress((void**)&pXhi, g_Xhi);
    cudaGetSymbolAddress((void**)&pXlo, g_Xlo);
    cudaGetSymbolAddress((void**)&pWhi, g_Whi);
    cudaGetSymbolAddress((void**)&pWlo, g_Wlo);

    int total4 = (MTOT * E + 3 * H * E) / 4;
    split_k<<<total4 / NT, NT>>>(X, Wq, Wk, Wv, pXhi, pXlo, pWhi, pWlo);

    qkv_mm<<<dim3(H / 128, MTOT / 128, 3), NT, SMEM_QKV>>>(bq, bk, bv);
    scores_mm<<<nsm, NT, SMEM_S3>>>(mask, out);
    softmax_k<<<NB * SQ, 256>>>();
    pv_mm<<<nsm, NT, SMEM_PV>>>(out);
}

// round 16
// speedup vs baseline: 1.4662x; 1.1282x over previous
#include <cuda_runtime.h>
#include <cuda_bf16.h>
#include <cuda_fp16.h>
#include <cstdint>
#include <math_constants.h>

#define E    1024
#define H    1024
#define SQ   4096
#define NB   2
#define MTOT 8192
#define NT   256
#define STAGE2    65536     // 2-stage buffer size (qkv)
#define SMEM_QKV  131072
#define STAGE_SC  49152     // scores: Qhi 16K + Qlo 16K + K 16K
#define SMEM_SC   147456
#define STAGE_PV  32768     // pv: A f16 16KB + B f16 16KB
#define SMEM_PV   98304

// ---------------------------------------------------------------------------
// Device scratch (allocation-free per harness rules)
// ---------------------------------------------------------------------------
__device__ __align__(256) __nv_bfloat16 g_Xhi[(size_t)MTOT * E];
__device__ __align__(256) __nv_bfloat16 g_Xlo[(size_t)MTOT * E];
__device__ __align__(256) __nv_bfloat16 g_Whi[(size_t)3 * H * E];
__device__ __align__(256) __nv_bfloat16 g_Wlo[(size_t)3 * H * E];
__device__ __align__(256) __half        g_Qhi16[(size_t)MTOT * H];  // Q fp16 hi
__device__ __align__(256) __half        g_Qlo16[(size_t)MTOT * H];  // Q fp16 lo
__device__ __align__(256) __half        g_K16 [(size_t)MTOT * H];   // K fp16 single
__device__ __align__(256) __half        g_Vt16[(size_t)NB * H * SQ]; // [b][h][s] fp16
__device__ __align__(256) float         g_P  [(size_t)NB * SQ * SQ];
__device__ __align__(256) __half        g_P16[(size_t)NB * SQ * SQ]; // fp16 softmax out

// ---------------------------------------------------------------------------
// Helpers
// ---------------------------------------------------------------------------
__device__ __forceinline__ uint32_t smem_u32(const void* p) {
    uint32_t a;
    asm("{ .reg .u64 t; cvta.to.shared.u64 t, %1; cvt.u32.u64 %0, t; }"
        : "=r"(a) : "l"(p));
    return a;
}

#define SWZ(o) ((o) ^ (((o) >> 3) & 0x70))

__device__ __forceinline__ void cpa16(uint32_t dst, const void* src) {
    asm volatile("cp.async.cg.shared.global [%0], [%1], 16;" :: "r"(dst), "l"(src));
}
#define CP_COMMIT() asm volatile("cp.async.commit_group;" ::: "memory")
#define CP_WAIT2()  asm volatile("cp.async.wait_group 2;" ::: "memory")
#define CP_WAIT1()  asm volatile("cp.async.wait_group 1;" ::: "memory")
#define CP_WAIT0()  asm volatile("cp.async.wait_group 0;" ::: "memory")

__device__ __forceinline__ void ldsm4(uint32_t r[4], uint32_t addr) {
    asm volatile("ldmatrix.sync.aligned.m8n8.x4.shared.b16 {%0,%1,%2,%3}, [%4];"
                 : "=r"(r[0]), "=r"(r[1]), "=r"(r[2]), "=r"(r[3]) : "r"(addr));
}

__device__ __forceinline__ void mma16816(float* d, const uint32_t* a,
                                         uint32_t b0, uint32_t b1) {
    asm volatile(
        "mma.sync.aligned.m16n8k16.row.col.f32.bf16.bf16.f32 "
        "{%0,%1,%2,%3}, {%4,%5,%6,%7}, {%8,%9}, {%0,%1,%2,%3};"
        : "+f"(d[0]), "+f"(d[1]), "+f"(d[2]), "+f"(d[3])
        : "r"(a[0]), "r"(a[1]), "r"(a[2]), "r"(a[3]), "r"(b0), "r"(b1));
}

__device__ __forceinline__ void mma16816h(float* d, const uint32_t* a,
                                          uint32_t b0, uint32_t b1) {
    asm volatile(
        "mma.sync.aligned.m16n8k16.row.col.f32.f16.f16.f32 "
        "{%0,%1,%2,%3}, {%4,%5,%6,%7}, {%8,%9}, {%0,%1,%2,%3};"
        : "+f"(d[0]), "+f"(d[1]), "+f"(d[2]), "+f"(d[3])
        : "r"(a[0]), "r"(a[1]), "r"(a[2]), "r"(a[3]), "r"(b0), "r"(b1));
}

__device__ __forceinline__ void split2(float a, float b,
                                       __nv_bfloat162& h, __nv_bfloat162& l2) {
    h = __float22bfloat162_rn(make_float2(a, b));
    float2 hf = __bfloat1622float2(h);
    l2 = __float22bfloat162_rn(make_float2(a - hf.x, b - hf.y));
}

__device__ __forceinline__ void split2h(float a, float b,
                                        __half2& h, __half2& l2) {
    h = __floats2half2_rn(a, b);
    float2 hf = __half22float2(h);
    l2 = __floats2half2_rn(a - hf.x, b - hf.y);
}

// Copy one 128x64 16-bit-elem tile (K-major) into SW128-swizzled smem
__device__ __forceinline__ void fill_copy(uint32_t dst, const void* __restrict__ srcv,
                                          size_t ld, int tid) {
    const __nv_bfloat16* src = (const __nv_bfloat16*)srcv;
    #pragma unroll
    for (int i = 0; i < 4; i++) {
        int s = tid + i * NT;
        int r = s >> 3, q = s & 7;
        cpa16(dst + SWZ((uint32_t)(r * 128 + q * 16)),
              src + (size_t)r * ld + q * 8);
    }
}

// bf16x3 MMA work for one 128x128 x K64 block (qkv).
// Stage layout: Ahi @0, Alo @16384, Bhi @32768, Blo @49152 (16KB each).
__device__ __forceinline__ void mma_k64(uint32_t base, uint32_t aoff,
                                        uint32_t boff, float (&acc)[2][8][4]) {
    #pragma unroll
    for (int c = 0; c < 4; c++) {
        uint32_t ao = 32u * c;
        uint32_t ahi[2][4], alo[2][4], bhi[4][4], blo[4][4];
        ldsm4(ahi[0], base +         SWZ(aoff + ao));
        ldsm4(ahi[1], base +         SWZ(aoff + 2048 + ao));
        ldsm4(alo[0], base + 16384 + SWZ(aoff + ao));
        ldsm4(alo[1], base + 16384 + SWZ(aoff + 2048 + ao));
        #pragma unroll
        for (int j = 0; j < 4; j++) {
            ldsm4(bhi[j], base + 32768 + SWZ(boff + j * 2048 + ao));
            ldsm4(blo[j], base + 49152 + SWZ(boff + j * 2048 + ao));
        }
        #pragma unroll
        for (int j = 0; j < 4; j++)
            #pragma unroll
            for (int mf = 0; mf < 2; mf++) {
                mma16816(acc[mf][2*j],     ahi[mf], bhi[j][0], bhi[j][1]);
                mma16816(acc[mf][2*j + 1], ahi[mf], bhi[j][2], bhi[j][3]);
            }
        #pragma unroll
        for (int j = 0; j < 4; j++)
            #pragma unroll
            for (int mf = 0; mf < 2; mf++) {
                mma16816(acc[mf][2*j],     ahi[mf], blo[j][0], blo[j][1]);
                mma16816(acc[mf][2*j + 1], ahi[mf], blo[j][2], blo[j][3]);
            }
        #pragma unroll
        for (int j = 0; j < 4; j++)
            #pragma unroll
            for (int mf = 0; mf < 2; mf++) {
                mma16816(acc[mf][2*j],     alo[mf], bhi[j][0], bhi[j][1]);
                mma16816(acc[mf][2*j + 1], alo[mf], bhi[j][2], bhi[j][3]);
            }
    }
}

// Asymmetric fp16 x2 MMA for one 128x128 x K64 block (scores).
// A = Q (hi @0, lo @16384), B = K single (@32768). 2 terms.
__device__ __forceinline__ void mma_k64_f16x2(uint32_t base, uint32_t aoff,
                                              uint32_t boff, float (&acc)[2][8][4]) {
    #pragma unroll
    for (int c = 0; c < 4; c++) {
        uint32_t ao = 32u * c;
        uint32_t ahi[2][4], alo[2][4], bh[4][4];
        ldsm4(ahi[0], base +         SWZ(aoff + ao));
        ldsm4(ahi[1], base +         SWZ(aoff + 2048 + ao));
        ldsm4(alo[0], base + 16384 + SWZ(aoff + ao));
        ldsm4(alo[1], base + 16384 + SWZ(aoff + 2048 + ao));
        #pragma unroll
        for (int j = 0; j < 4; j++)
            ldsm4(bh[j], base + 32768 + SWZ(boff + j * 2048 + ao));
        #pragma unroll
        for (int j = 0; j < 4; j++)
            #pragma unroll
            for (int mf = 0; mf < 2; mf++) {
                mma16816h(acc[mf][2*j],     ahi[mf], bh[j][0], bh[j][1]);
                mma16816h(acc[mf][2*j + 1], ahi[mf], bh[j][2], bh[j][3]);
            }
        #pragma unroll
        for (int j = 0; j < 4; j++)
            #pragma unroll
            for (int mf = 0; mf < 2; mf++) {
                mma16816h(acc[mf][2*j],     alo[mf], bh[j][0], bh[j][1]);
                mma16816h(acc[mf][2*j + 1], alo[mf], bh[j][2], bh[j][3]);
            }
    }
}

// Single-term fp16 MMA for one 128x128 x K64 block (pv).
// Stage layout: A(f16) @0 (16KB), B(f16) @16384.
__device__ __forceinline__ void mma_k64_f16(uint32_t base, uint32_t aoff,
                                            uint32_t boff, float (&acc)[2][8][4]) {
    #pragma unroll
    for (int c = 0; c < 4; c++) {
        uint32_t ao = 32u * c;
        uint32_t ah[2][4], bh[4][4];
        ldsm4(ah[0], base + SWZ(aoff + ao));
        ldsm4(ah[1], base + SWZ(aoff + 2048 + ao));
        #pragma unroll
        for (int j = 0; j < 4; j++)
            ldsm4(bh[j], base + 16384 + SWZ(boff + j * 2048 + ao));
        #pragma unroll
        for (int j = 0; j < 4; j++)
            #pragma unroll
            for (int mf = 0; mf < 2; mf++) {
                mma16816h(acc[mf][2*j],     ah[mf], bh[j][0], bh[j][1]);
                mma16816h(acc[mf][2*j + 1], ah[mf], bh[j][2], bh[j][3]);
            }
    }
}

// ---------------------------------------------------------------------------
// qkv: 2-stage non-persistent GEMM (proven structure)
// ---------------------------------------------------------------------------
__device__ __forceinline__ void gemm_main2(
    const __nv_bfloat16* __restrict__ Ah, const __nv_bfloat16* __restrict__ Al,
    const __nv_bfloat16* __restrict__ Bh, const __nv_bfloat16* __restrict__ Bl,
    size_t lda, size_t ldb, int nkb, uint32_t sbuf, float (&acc)[2][8][4])
{
    const int tid = threadIdx.x, l = tid & 31, wid = tid >> 5;
    const int mw = (wid >> 1) * 32, nw = (wid & 1) * 64;
    const uint32_t aoff = (uint32_t)((mw + (l & 15)) * 128 + ((l >> 4) & 1) * 16);
    const uint32_t boff = (uint32_t)((nw + (l & 7) + ((l >> 4) & 1) * 8) * 128 +
                                     ((l >> 3) & 1) * 16);

    fill_copy(sbuf,         Ah, lda, tid);
    fill_copy(sbuf + 16384, Al, lda, tid);
    fill_copy(sbuf + 32768, Bh, ldb, tid);
    fill_copy(sbuf + 49152, Bl, ldb, tid);
    CP_COMMIT();

    for (int kb = 0; kb < nkb; kb++) {
        if (kb + 1 < nkb) {
            uint32_t nbuf = sbuf + ((kb + 1) & 1) * STAGE2;
            size_t ko = (size_t)(kb + 1) * 64;
            fill_copy(nbuf,         Ah + ko, lda, tid);
            fill_copy(nbuf + 16384, Al + ko, lda, tid);
            fill_copy(nbuf + 32768, Bh + ko, ldb, tid);
            fill_copy(nbuf + 49152, Bl + ko, ldb, tid);
            CP_COMMIT();
            CP_WAIT1();
        } else {
            CP_WAIT0();
        }
        __syncthreads();
        mma_k64(sbuf + (kb & 1) * STAGE2, aoff, boff, acc);
        __syncthreads();
    }
}

__device__ __forceinline__ void store_stage(float* stage, float (&acc)[2][8][4]) {
    const int tid = threadIdx.x, l = tid & 31, wid = tid >> 5;
    const int mw = (wid >> 1) * 32, nw = (wid & 1) * 64;
    const int r0 = mw + (l >> 2), c0 = nw + (l & 3) * 2;
    #pragma unroll
    for (int mf = 0; mf < 2; mf++)
        #pragma unroll
        for (int nf = 0; nf < 8; nf++) {
            int cc = c0 + nf * 8;
            *(float2*)&stage[(r0 + mf * 16) * 132 + cc] =
                make_float2(acc[mf][nf][0], acc[mf][nf][1]);
            *(float2*)&stage[(r0 + mf * 16 + 8) * 132 + cc] =
                make_float2(acc[mf][nf][2], acc[mf][nf][3]);
        }
}

// ---------------------------------------------------------------------------
// Split fp32 -> (hi, lo) bf16. Region 0 = X, regions 1..3 = Wq/Wk/Wv.
// ---------------------------------------------------------------------------
__global__ __launch_bounds__(NT) void split_k(const float* __restrict__ X,
                                              const float* __restrict__ Wq,
                                              const float* __restrict__ Wk,
                                              const float* __restrict__ Wv,
                                              __nv_bfloat16* __restrict__ Xhi,
                                              __nv_bfloat16* __restrict__ Xlo,
                                              __nv_bfloat16* __restrict__ Whi,
                                              __nv_bfloat16* __restrict__ Wlo)
{
    const int nx = MTOT * E / 4;
    const int nw = H * E / 4;
    int i = blockIdx.x * NT + threadIdx.x;
    const float* src;
    __nv_bfloat16 *hi, *lo;
    int j;
    if (i < nx) {
        src = X; hi = Xhi; lo = Xlo; j = i;
    } else {
        int t = i - nx;
        int w = t / nw;
        j = t - w * nw;
        src = (w == 0) ? Wq : (w == 1) ? Wk : Wv;
        hi = Whi + (size_t)w * H * E;
        lo = Wlo + (size_t)w * H * E;
    }
    float4 v = ((const float4*)src)[j];
    __nv_bfloat162 h0, l0, h1, l1;
    split2(v.x, v.y, h0, l0);
    split2(v.z, v.w, h1, l1);
    ((__nv_bfloat162*)hi)[2 * j]     = h0;
    ((__nv_bfloat162*)hi)[2 * j + 1] = h1;
    ((__nv_bfloat162*)lo)[2 * j]     = l0;
    ((__nv_bfloat162*)lo)[2 * j + 1] = l1;
}

// ---------------------------------------------------------------------------
// QKV projection GEMM. grid (H/128, MTOT/128, 3)
// z==0: Q -> fp16 hi/lo. z==1: K -> fp16 single. z==2: V^T -> fp16 single.
// ---------------------------------------------------------------------------
__global__ __launch_bounds__(NT) void qkv_mm(const float* __restrict__ bq,
                                             const float* __restrict__ bk,
                                             const float* __restrict__ bv)
{
    extern __shared__ char dsm[];
    uint32_t sbuf = smem_u32(dsm);
    const int tid = threadIdx.x;
    const int z = blockIdx.z, row0 = blockIdx.y * 128, col0 = blockIdx.x * 128;

    const __nv_bfloat16* Ah = g_Xhi + (size_t)row0 * E;
    const __nv_bfloat16* Al = g_Xlo + (size_t)row0 * E;
    const __nv_bfloat16* Bh = g_Whi + ((size_t)z * H + col0) * E;
    const __nv_bfloat16* Bl = g_Wlo + ((size_t)z * H + col0) * E;

    float acc[2][8][4] = {};
    gemm_main2(Ah, Al, Bh, Bl, E, E, E / 64, sbuf, acc);

    float* stage = (float*)dsm;
    store_stage(stage, acc);
    __syncthreads();

    const float* bias = (z == 0) ? bq : (z == 1) ? bk : bv;

    if (z == 0) {
        #pragma unroll
        for (int i = 0; i < 32; i++) {
            int s = tid + i * NT;          // 0..8191 pair slots
            int m = s >> 6, c2 = (s & 63) * 2;
            float a = stage[m * 132 + c2]     + __ldg(&bias[col0 + c2]);
            float b = stage[m * 132 + c2 + 1] + __ldg(&bias[col0 + c2 + 1]);
            __half2 h, l2;
            split2h(a, b, h, l2);
            size_t idx = ((size_t)(row0 + m) * H + col0 + c2) >> 1;
            ((__half2*)g_Qhi16)[idx] = h;
            ((__half2*)g_Qlo16)[idx] = l2;
        }
    } else if (z == 1) {
        #pragma unroll
        for (int i = 0; i < 32; i++) {
            int s = tid + i * NT;
            int m = s >> 6, c2 = (s & 63) * 2;
            float a = stage[m * 132 + c2]     + __ldg(&bias[col0 + c2]);
            float b = stage[m * 132 + c2 + 1] + __ldg(&bias[col0 + c2 + 1]);
            size_t idx = ((size_t)(row0 + m) * H + col0 + c2) >> 1;
            ((__half2*)g_K16)[idx] = __floats2half2_rn(a, b);
        }
    } else {
        // V: write transposed [b][h][s], single fp16
        #pragma unroll
        for (int i = 0; i < 32; i++) {
            int p = tid + i * NT;          // 0..8191 pair slots
            int c = p >> 6, mp = (p & 63) * 2;
            float bs = __ldg(&bias[col0 + c]);
            float a = stage[mp * 132 + c] + bs;
            float b = stage[(mp + 1) * 132 + c] + bs;
            size_t idx = (((size_t)(row0 >> 12) * H + col0 + c) * SQ +
                          (row0 & 4095) + mp) >> 1;
            ((__half2*)g_Vt16)[idx] = __floats2half2_rn(a, b);
        }
    }
}

// ---------------------------------------------------------------------------
// Scores: persistent 3-stage streamed asymmetric fp16x2 GEMM.
// P = (Qhi+Qlo) K^T * scale, masked. Zeroes `out` for pv atomics.
// ---------------------------------------------------------------------------
__global__ __launch_bounds__(NT) void scores_mm(const int* __restrict__ mask,
                                                float* __restrict__ outz)
{
    extern __shared__ char dsm[];
    uint32_t sbuf = smem_u32(dsm);
    const int tid = threadIdx.x, l = tid & 31, wid = tid >> 5;
    const int mw = (wid >> 1) * 32, nw = (wid & 1) * 64;
    const uint32_t aoff = (uint32_t)((mw + (l & 15)) * 128 + ((l >> 4) & 1) * 16);
    const uint32_t boff = (uint32_t)((nw + (l & 7) + ((l >> 4) & 1) * 8) * 128 +
                                     ((l >> 3) & 1) * 16);
    const int G = gridDim.x;
    const int NTILES = (SQ / 128) * (SQ / 128) * NB;   // 2048
    const int NKB = H / 64;                             // 16

    int t_f = blockIdx.x, kb_f = 0, fp = 0;

    auto fill_step = [&]() {
        if (t_f < NTILES) {
            int bz = t_f >> 10, rem = t_f & 1023;
            int row0 = (rem >> 5) << 7, col0 = (rem & 31) << 7;
            size_t ko = (size_t)kb_f * 64;
            uint32_t b = sbuf + (uint32_t)(fp % 3) * STAGE_SC;
            fill_copy(b,         g_Qhi16 + ((size_t)(bz * SQ + row0)) * H + ko, H, tid);
            fill_copy(b + 16384, g_Qlo16 + ((size_t)(bz * SQ + row0)) * H + ko, H, tid);
            fill_copy(b + 32768, g_K16   + ((size_t)(bz * SQ + col0)) * H + ko, H, tid);
        }
        CP_COMMIT();
        fp++;
        if (++kb_f == NKB) { kb_f = 0; t_f += G; }
    };
    fill_step();
    fill_step();

    // Zero `out` for pv's atomic split-K reduction (hidden under MMA).
    {
        const int n4 = MTOT * H / 4;
        for (int i = blockIdx.x * NT + tid; i < n4; i += G * NT)
            ((float4*)outz)[i] = make_float4(0.f, 0.f, 0.f, 0.f);
    }

    float acc[2][8][4] = {};
    int cp = 0;
    const float scale = 0.03125f;  // 1/sqrt(1024)
    const int r0 = mw + (l >> 2), c0 = nw + (l & 3) * 2;

    for (int t = blockIdx.x; t < NTILES; t += G) {
        for (int kb = 0; kb < NKB; kb++) {
            fill_step();
            CP_WAIT2();
            __syncthreads();
            mma_k64_f16x2(sbuf + (uint32_t)(cp % 3) * STAGE_SC, aoff, boff, acc);
            __syncthreads();
            cp++;
        }
        int bz = t >> 10, rem = t & 1023;
        int row0 = (rem >> 5) << 7, col0 = (rem & 31) << 7;
        const size_t pbase = (size_t)bz * SQ * SQ;
        #pragma unroll
        for (int mf = 0; mf < 2; mf++)
            #pragma unroll
            for (int nf = 0; nf < 8; nf++)
                #pragma unroll
                for (int hh = 0; hh < 2; hh++) {
                    int r = row0 + r0 + mf * 16 + hh * 8;
                    int c = col0 + c0 + nf * 8;
                    size_t gi = pbase + (size_t)r * SQ + c;
                    int2 mk = __ldg((const int2*)(mask + gi));
                    float2 v;
                    v.x = (mk.x == 0) ? -CUDART_INF_F : acc[mf][nf][hh*2]     * scale;
                    v.y = (mk.y == 0) ? -CUDART_INF_F : acc[mf][nf][hh*2 + 1] * scale;
                    *(float2*)(g_P + gi) = v;
                    acc[mf][nf][hh*2] = 0.0f;
                    acc[mf][nf][hh*2 + 1] = 0.0f;
                }
    }
}

// ---------------------------------------------------------------------------
// Row softmax of g_P -> fp16 P. One block per row; row in registers.
// ---------------------------------------------------------------------------
__global__ __launch_bounds__(256) void softmax_k()
{
    __shared__ float red[8];
    const int tid = threadIdx.x;
    const float* p = g_P + (size_t)blockIdx.x * SQ;

    float4 v[4];
    float m = -CUDART_INF_F;
    #pragma unroll
    for (int i = 0; i < 4; i++) {
        v[i] = __ldg((const float4*)(p + (size_t)(i * 256 + tid) * 4));
        m = fmaxf(m, fmaxf(fmaxf(v[i].x, v[i].y), fmaxf(v[i].z, v[i].w)));
    }
    #pragma unroll
    for (int o = 16; o; o >>= 1) m = fmaxf(m, __shfl_xor_sync(0xFFFFFFFFu, m, o));
    if ((tid & 31) == 0) red[tid >> 5] = m;
    __syncthreads();
    m = fmaxf(fmaxf(fmaxf(red[0], red[1]), fmaxf(red[2], red[3])),
              fmaxf(fmaxf(red[4], red[5]), fmaxf(red[6], red[7])));
    __syncthreads();

    float s = 0.0f;
    #pragma unroll
    for (int i = 0; i < 4; i++) {
        v[i].x = __expf(v[i].x - m); v[i].y = __expf(v[i].y - m);
        v[i].z = __expf(v[i].z - m); v[i].w = __expf(v[i].w - m);
        s += (v[i].x + v[i].y) + (v[i].z + v[i].w);
    }
    #pragma unroll
    for (int o = 16; o; o >>= 1) s += __shfl_xor_sync(0xFFFFFFFFu, s, o);
    if ((tid & 31) == 0) red[tid >> 5] = s;
    __syncthreads();
    s = ((red[0] + red[1]) + (red[2] + red[3])) +
        ((red[4] + red[5]) + (red[6] + red[7]));
    float inv = 1.0f / s;

    size_t r2 = (size_t)blockIdx.x * (SQ / 2);
    #pragma unroll
    for (int i = 0; i < 4; i++) {
        int base = (i * 256 + tid) * 2;
        ((__half2*)g_P16)[r2 + base]     = __floats2half2_rn(v[i].x * inv, v[i].y * inv);
        ((__half2*)g_P16)[r2 + base + 1] = __floats2half2_rn(v[i].z * inv, v[i].w * inv);
    }
}

// ---------------------------------------------------------------------------
// PV: persistent 3-stage streamed fp16 GEMM with SPLIT-K-2.
// Single-term P(f16) x V(f16), fp32 accum. Atomic reduction into `out`.
// ---------------------------------------------------------------------------
__global__ __launch_bounds__(NT) void pv_mm(float* __restrict__ out)
{
    extern __shared__ char dsm[];
    uint32_t sbuf = smem_u32(dsm);
    const int tid = threadIdx.x, l = tid & 31, wid = tid >> 5;
    const int mw = (wid >> 1) * 32, nw = (wid & 1) * 64;
    const uint32_t aoff = (uint32_t)((mw + (l & 15)) * 128 + ((l >> 4) & 1) * 16);
    const uint32_t boff = (uint32_t)((nw + (l & 7) + ((l >> 4) & 1) * 8) * 128 +
                                     ((l >> 3) & 1) * 16);
    const int G = gridDim.x;
    const int NUNITS = (H / 128) * (SQ / 128) * NB * 2;  // 1024
    const int NKB = SQ / 128;                             // 32 k-blocks per unit

    int t_f = blockIdx.x, kb_f = 0, fp = 0;

    auto fill_step = [&]() {
        if (t_f < NUNITS) {
            int tt = t_f >> 1, kh = t_f & 1;
            int bz = tt >> 8, rem = tt & 255;
            int row0 = (rem >> 3) << 7, col0 = (rem & 7) << 7;
            size_t ko = (size_t)(kh * NKB + kb_f) * 64;
            uint32_t b = sbuf + (uint32_t)(fp % 3) * STAGE_PV;
            fill_copy(b,         g_P16  + (size_t)bz * SQ * SQ +
                                 (size_t)row0 * SQ + ko, SQ, tid);
            fill_copy(b + 16384, g_Vt16 + ((size_t)bz * H + col0) * SQ + ko, SQ, tid);
        }
        CP_COMMIT();
        fp++;
        if (++kb_f == NKB) { kb_f = 0; t_f += G; }
    };
    fill_step();
    fill_step();

    float acc[2][8][4] = {};
    int cp = 0;
    const int r0 = mw + (l >> 2), c0 = nw + (l & 3) * 2;

    for (int u = blockIdx.x; u < NUNITS; u += G) {
        for (int kb = 0; kb < NKB; kb++) {
            fill_step();
            CP_WAIT2();
            __syncthreads();
            mma_k64_f16(sbuf + (uint32_t)(cp % 3) * STAGE_PV, aoff, boff, acc);
            __syncthreads();
            cp++;
        }
        int tt = u >> 1;
        int bz = tt >> 8, rem = tt & 255;
        int row0 = (rem >> 3) << 7, col0 = (rem & 7) << 7;
        #pragma unroll
        for (int mf = 0; mf < 2; mf++)
            #pragma unroll
            for (int nf = 0; nf < 8; nf++)
                #pragma unroll
                for (int hh = 0; hh < 2; hh++) {
                    int r = row0 + r0 + mf * 16 + hh * 8;
                    int c = col0 + c0 + nf * 8;
                    float* o = &out[((size_t)bz * SQ + r) * H + c];
                    atomicAdd(o,     acc[mf][nf][hh*2]);
                    atomicAdd(o + 1, acc[mf][nf][hh*2 + 1]);
                    acc[mf][nf][hh*2] = 0.0f;
                    acc[mf][nf][hh*2 + 1] = 0.0f;
                }
    }
}

// ---------------------------------------------------------------------------
extern "C" void kernel_launch(void* const* d_in, const int* in_sizes, int n_in,
                              void* d_out, int out_size)
{
    const float* X    = (const float*)d_in[0];
    const int*   mask = (const int*)  d_in[1];
    const float* Wq   = (const float*)d_in[2];
    const float* bq   = (const float*)d_in[3];
    const float* Wk   = (const float*)d_in[4];
    const float* bk   = (const float*)d_in[5];
    const float* Wv   = (const float*)d_in[6];
    const float* bv   = (const float*)d_in[7];
    float* out = (float*)d_out;

    cudaFuncSetAttribute(qkv_mm,    cudaFuncAttributeMaxDynamicSharedMemorySize, SMEM_QKV);
    cudaFuncSetAttribute(scores_mm, cudaFuncAttributeMaxDynamicSharedMemorySize, SMEM_SC);
    cudaFuncSetAttribute(pv_mm,     cudaFuncAttributeMaxDynamicSharedMemorySize, SMEM_PV);

    int dev = 0, nsm = 148;
    cudaGetDevice(&dev);
    cudaDeviceGetAttribute(&nsm, cudaDevAttrMultiProcessorCount, dev);

    __nv_bfloat16 *pXhi, *pXlo, *pWhi, *pWlo;
    cudaGetSymbolAddress((void**)&pXhi, g_Xhi);
    cudaGetSymbolAddress((void**)&pXlo, g_Xlo);
    cudaGetSymbolAddress((void**)&pWhi, g_Whi);
    cudaGetSymbolAddress((void**)&pWlo, g_Wlo);

    int total4 = (MTOT * E + 3 * H * E) / 4;
    split_k<<<total4 / NT, NT>>>(X, Wq, Wk, Wv, pXhi, pXlo, pWhi, pWlo);

    qkv_mm<<<dim3(H / 128, MTOT / 128, 3), NT, SMEM_QKV>>>(bq, bk, bv);
    scores_mm<<<nsm, NT, SMEM_SC>>>(mask, out);
    softmax_k<<<NB * SQ, 256>>>();
    pv_mm<<<nsm, NT, SMEM_PV>>>(out);
}

// round 17
// speedup vs baseline: 1.6243x; 1.1078x over previous
#include <cuda_runtime.h>
#include <cuda_bf16.h>
#include <cuda_fp16.h>
#include <cstdint>
#include <math_constants.h>

#define E    1024
#define H    1024
#define SQ   4096
#define NB   2
#define MTOT 8192
#define NT   256
#define STAGE_QK  49152     // qkv: Xhi 16K + Xlo 16K + W 16K
#define SMEM_QKV  98304
#define STAGE_SC  49152     // scores: Qhi 16K + Qlo 16K + K 16K
#define SMEM_SC   147456
#define STAGE_PV  32768     // pv: A f16 16KB + B f16 16KB
#define SMEM_PV   98304

// ---------------------------------------------------------------------------
// Device scratch (allocation-free per harness rules)
// ---------------------------------------------------------------------------
__device__ __align__(256) __half g_Xhi16[(size_t)MTOT * E];   // X fp16 hi
__device__ __align__(256) __half g_Xlo16[(size_t)MTOT * E];   // X fp16 lo
__device__ __align__(256) __half g_W16 [(size_t)3 * H * E];   // W fp16 single
__device__ __align__(256) __half g_Qhi16[(size_t)MTOT * H];   // Q fp16 hi
__device__ __align__(256) __half g_Qlo16[(size_t)MTOT * H];   // Q fp16 lo
__device__ __align__(256) __half g_K16 [(size_t)MTOT * H];    // K fp16 single
__device__ __align__(256) __half g_Vt16[(size_t)NB * H * SQ]; // [b][h][s] fp16
__device__ __align__(256) float  g_P  [(size_t)NB * SQ * SQ];
__device__ __align__(256) __half g_P16[(size_t)NB * SQ * SQ]; // fp16 softmax out

// ---------------------------------------------------------------------------
// Helpers
// ---------------------------------------------------------------------------
__device__ __forceinline__ uint32_t smem_u32(const void* p) {
    uint32_t a;
    asm("{ .reg .u64 t; cvta.to.shared.u64 t, %1; cvt.u32.u64 %0, t; }"
        : "=r"(a) : "l"(p));
    return a;
}

#define SWZ(o) ((o) ^ (((o) >> 3) & 0x70))

__device__ __forceinline__ void cpa16(uint32_t dst, const void* src) {
    asm volatile("cp.async.cg.shared.global [%0], [%1], 16;" :: "r"(dst), "l"(src));
}
#define CP_COMMIT() asm volatile("cp.async.commit_group;" ::: "memory")
#define CP_WAIT2()  asm volatile("cp.async.wait_group 2;" ::: "memory")
#define CP_WAIT1()  asm volatile("cp.async.wait_group 1;" ::: "memory")
#define CP_WAIT0()  asm volatile("cp.async.wait_group 0;" ::: "memory")

__device__ __forceinline__ void ldsm4(uint32_t r[4], uint32_t addr) {
    asm volatile("ldmatrix.sync.aligned.m8n8.x4.shared.b16 {%0,%1,%2,%3}, [%4];"
                 : "=r"(r[0]), "=r"(r[1]), "=r"(r[2]), "=r"(r[3]) : "r"(addr));
}

__device__ __forceinline__ void mma16816h(float* d, const uint32_t* a,
                                          uint32_t b0, uint32_t b1) {
    asm volatile(
        "mma.sync.aligned.m16n8k16.row.col.f32.f16.f16.f32 "
        "{%0,%1,%2,%3}, {%4,%5,%6,%7}, {%8,%9}, {%0,%1,%2,%3};"
        : "+f"(d[0]), "+f"(d[1]), "+f"(d[2]), "+f"(d[3])
        : "r"(a[0]), "r"(a[1]), "r"(a[2]), "r"(a[3]), "r"(b0), "r"(b1));
}

__device__ __forceinline__ void split2h(float a, float b,
                                        __half2& h, __half2& l2) {
    h = __floats2half2_rn(a, b);
    float2 hf = __half22float2(h);
    l2 = __floats2half2_rn(a - hf.x, b - hf.y);
}

// Copy one 128x64 16-bit-elem tile (K-major) into SW128-swizzled smem
__device__ __forceinline__ void fill_copy(uint32_t dst, const void* __restrict__ srcv,
                                          size_t ld, int tid) {
    const __half* src = (const __half*)srcv;
    #pragma unroll
    for (int i = 0; i < 4; i++) {
        int s = tid + i * NT;
        int r = s >> 3, q = s & 7;
        cpa16(dst + SWZ((uint32_t)(r * 128 + q * 16)),
              src + (size_t)r * ld + q * 8);
    }
}

// Asymmetric fp16 x2 MMA for one 128x128 x K64 block.
// A = (hi @0, lo @16384), B = single (@32768). 2 terms.
__device__ __forceinline__ void mma_k64_f16x2(uint32_t base, uint32_t aoff,
                                              uint32_t boff, float (&acc)[2][8][4]) {
    #pragma unroll
    for (int c = 0; c < 4; c++) {
        uint32_t ao = 32u * c;
        uint32_t ahi[2][4], alo[2][4], bh[4][4];
        ldsm4(ahi[0], base +         SWZ(aoff + ao));
        ldsm4(ahi[1], base +         SWZ(aoff + 2048 + ao));
        ldsm4(alo[0], base + 16384 + SWZ(aoff + ao));
        ldsm4(alo[1], base + 16384 + SWZ(aoff + 2048 + ao));
        #pragma unroll
        for (int j = 0; j < 4; j++)
            ldsm4(bh[j], base + 32768 + SWZ(boff + j * 2048 + ao));
        #pragma unroll
        for (int j = 0; j < 4; j++)
            #pragma unroll
            for (int mf = 0; mf < 2; mf++) {
                mma16816h(acc[mf][2*j],     ahi[mf], bh[j][0], bh[j][1]);
                mma16816h(acc[mf][2*j + 1], ahi[mf], bh[j][2], bh[j][3]);
            }
        #pragma unroll
        for (int j = 0; j < 4; j++)
            #pragma unroll
            for (int mf = 0; mf < 2; mf++) {
                mma16816h(acc[mf][2*j],     alo[mf], bh[j][0], bh[j][1]);
                mma16816h(acc[mf][2*j + 1], alo[mf], bh[j][2], bh[j][3]);
            }
    }
}

// Single-term fp16 MMA for one 128x128 x K64 block (pv).
// Stage layout: A(f16) @0 (16KB), B(f16) @16384.
__device__ __forceinline__ void mma_k64_f16(uint32_t base, uint32_t aoff,
                                            uint32_t boff, float (&acc)[2][8][4]) {
    #pragma unroll
    for (int c = 0; c < 4; c++) {
        uint32_t ao = 32u * c;
        uint32_t ah[2][4], bh[4][4];
        ldsm4(ah[0], base + SWZ(aoff + ao));
        ldsm4(ah[1], base + SWZ(aoff + 2048 + ao));
        #pragma unroll
        for (int j = 0; j < 4; j++)
            ldsm4(bh[j], base + 16384 + SWZ(boff + j * 2048 + ao));
        #pragma unroll
        for (int j = 0; j < 4; j++)
            #pragma unroll
            for (int mf = 0; mf < 2; mf++) {
                mma16816h(acc[mf][2*j],     ah[mf], bh[j][0], bh[j][1]);
                mma16816h(acc[mf][2*j + 1], ah[mf], bh[j][2], bh[j][3]);
            }
    }
}

__device__ __forceinline__ void store_stage(float* stage, float (&acc)[2][8][4]) {
    const int tid = threadIdx.x, l = tid & 31, wid = tid >> 5;
    const int mw = (wid >> 1) * 32, nw = (wid & 1) * 64;
    const int r0 = mw + (l >> 2), c0 = nw + (l & 3) * 2;
    #pragma unroll
    for (int mf = 0; mf < 2; mf++)
        #pragma unroll
        for (int nf = 0; nf < 8; nf++) {
            int cc = c0 + nf * 8;
            *(float2*)&stage[(r0 + mf * 16) * 132 + cc] =
                make_float2(acc[mf][nf][0], acc[mf][nf][1]);
            *(float2*)&stage[(r0 + mf * 16 + 8) * 132 + cc] =
                make_float2(acc[mf][nf][2], acc[mf][nf][3]);
        }
}

// ---------------------------------------------------------------------------
// Split fp32 inputs. X -> fp16 hi/lo; Wq/Wk/Wv -> single fp16.
// ---------------------------------------------------------------------------
__global__ __launch_bounds__(NT) void split_k(const float* __restrict__ X,
                                              const float* __restrict__ Wq,
                                              const float* __restrict__ Wk,
                                              const float* __restrict__ Wv)
{
    const int nx = MTOT * E / 4;
    const int nw = H * E / 4;
    int i = blockIdx.x * NT + threadIdx.x;
    if (i < nx) {
        float4 v = ((const float4*)X)[i];
        __half2 h0, l0, h1, l1;
        split2h(v.x, v.y, h0, l0);
        split2h(v.z, v.w, h1, l1);
        ((__half2*)g_Xhi16)[2 * i]     = h0;
        ((__half2*)g_Xhi16)[2 * i + 1] = h1;
        ((__half2*)g_Xlo16)[2 * i]     = l0;
        ((__half2*)g_Xlo16)[2 * i + 1] = l1;
    } else {
        int t = i - nx;
        int w = t / nw;
        int j = t - w * nw;
        const float* src = (w == 0) ? Wq : (w == 1) ? Wk : Wv;
        float4 v = ((const float4*)src)[j];
        size_t base = (size_t)w * (H * E / 2) + 2 * (size_t)j;
        ((__half2*)g_W16)[base]     = __floats2half2_rn(v.x, v.y);
        ((__half2*)g_W16)[base + 1] = __floats2half2_rn(v.z, v.w);
    }
}

// ---------------------------------------------------------------------------
// QKV projection GEMM: asymmetric fp16x2, 2-stage. grid (H/128, MTOT/128, 3)
// z==0: Q -> fp16 hi/lo. z==1: K -> fp16 single. z==2: V^T -> fp16 single.
// ---------------------------------------------------------------------------
__global__ __launch_bounds__(NT) void qkv_mm(const float* __restrict__ bq,
                                             const float* __restrict__ bk,
                                             const float* __restrict__ bv)
{
    extern __shared__ char dsm[];
    uint32_t sbuf = smem_u32(dsm);
    const int tid = threadIdx.x, l = tid & 31, wid = tid >> 5;
    const int mw = (wid >> 1) * 32, nw = (wid & 1) * 64;
    const uint32_t aoff = (uint32_t)((mw + (l & 15)) * 128 + ((l >> 4) & 1) * 16);
    const uint32_t boff = (uint32_t)((nw + (l & 7) + ((l >> 4) & 1) * 8) * 128 +
                                     ((l >> 3) & 1) * 16);
    const int z = blockIdx.z, row0 = blockIdx.y * 128, col0 = blockIdx.x * 128;

    const __half* Ah = g_Xhi16 + (size_t)row0 * E;
    const __half* Al = g_Xlo16 + (size_t)row0 * E;
    const __half* Bw = g_W16 + ((size_t)z * H + col0) * E;

    float acc[2][8][4] = {};

    fill_copy(sbuf,         Ah, E, tid);
    fill_copy(sbuf + 16384, Al, E, tid);
    fill_copy(sbuf + 32768, Bw, E, tid);
    CP_COMMIT();

    const int nkb = E / 64;
    for (int kb = 0; kb < nkb; kb++) {
        if (kb + 1 < nkb) {
            uint32_t nbuf = sbuf + ((kb + 1) & 1) * STAGE_QK;
            size_t ko = (size_t)(kb + 1) * 64;
            fill_copy(nbuf,         Ah + ko, E, tid);
            fill_copy(nbuf + 16384, Al + ko, E, tid);
            fill_copy(nbuf + 32768, Bw + ko, E, tid);
            CP_COMMIT();
            CP_WAIT1();
        } else {
            CP_WAIT0();
        }
        __syncthreads();
        mma_k64_f16x2(sbuf + (kb & 1) * STAGE_QK, aoff, boff, acc);
        __syncthreads();
    }

    float* stage = (float*)dsm;
    store_stage(stage, acc);
    __syncthreads();

    const float* bias = (z == 0) ? bq : (z == 1) ? bk : bv;

    if (z == 0) {
        #pragma unroll
        for (int i = 0; i < 32; i++) {
            int s = tid + i * NT;          // 0..8191 pair slots
            int m = s >> 6, c2 = (s & 63) * 2;
            float a = stage[m * 132 + c2]     + __ldg(&bias[col0 + c2]);
            float b = stage[m * 132 + c2 + 1] + __ldg(&bias[col0 + c2 + 1]);
            __half2 h, l2;
            split2h(a, b, h, l2);
            size_t idx = ((size_t)(row0 + m) * H + col0 + c2) >> 1;
            ((__half2*)g_Qhi16)[idx] = h;
            ((__half2*)g_Qlo16)[idx] = l2;
        }
    } else if (z == 1) {
        #pragma unroll
        for (int i = 0; i < 32; i++) {
            int s = tid + i * NT;
            int m = s >> 6, c2 = (s & 63) * 2;
            float a = stage[m * 132 + c2]     + __ldg(&bias[col0 + c2]);
            float b = stage[m * 132 + c2 + 1] + __ldg(&bias[col0 + c2 + 1]);
            size_t idx = ((size_t)(row0 + m) * H + col0 + c2) >> 1;
            ((__half2*)g_K16)[idx] = __floats2half2_rn(a, b);
        }
    } else {
        // V: write transposed [b][h][s], single fp16
        #pragma unroll
        for (int i = 0; i < 32; i++) {
            int p = tid + i * NT;          // 0..8191 pair slots
            int c = p >> 6, mp = (p & 63) * 2;
            float bs = __ldg(&bias[col0 + c]);
            float a = stage[mp * 132 + c] + bs;
            float b = stage[(mp + 1) * 132 + c] + bs;
            size_t idx = (((size_t)(row0 >> 12) * H + col0 + c) * SQ +
                          (row0 & 4095) + mp) >> 1;
            ((__half2*)g_Vt16)[idx] = __floats2half2_rn(a, b);
        }
    }
}

// ---------------------------------------------------------------------------
// Scores: persistent 3-stage streamed asymmetric fp16x2 GEMM.
// P = (Qhi+Qlo) K^T * scale, masked. Zeroes `out` for pv atomics.
// ---------------------------------------------------------------------------
__global__ __launch_bounds__(NT) void scores_mm(const int* __restrict__ mask,
                                                float* __restrict__ outz)
{
    extern __shared__ char dsm[];
    uint32_t sbuf = smem_u32(dsm);
    const int tid = threadIdx.x, l = tid & 31, wid = tid >> 5;
    const int mw = (wid >> 1) * 32, nw = (wid & 1) * 64;
    const uint32_t aoff = (uint32_t)((mw + (l & 15)) * 128 + ((l >> 4) & 1) * 16);
    const uint32_t boff = (uint32_t)((nw + (l & 7) + ((l >> 4) & 1) * 8) * 128 +
                                     ((l >> 3) & 1) * 16);
    const int G = gridDim.x;
    const int NTILES = (SQ / 128) * (SQ / 128) * NB;   // 2048
    const int NKB = H / 64;                             // 16

    int t_f = blockIdx.x, kb_f = 0, fp = 0;

    auto fill_step = [&]() {
        if (t_f < NTILES) {
            int bz = t_f >> 10, rem = t_f & 1023;
            int row0 = (rem >> 5) << 7, col0 = (rem & 31) << 7;
            size_t ko = (size_t)kb_f * 64;
            uint32_t b = sbuf + (uint32_t)(fp % 3) * STAGE_SC;
            fill_copy(b,         g_Qhi16 + ((size_t)(bz * SQ + row0)) * H + ko, H, tid);
            fill_copy(b + 16384, g_Qlo16 + ((size_t)(bz * SQ + row0)) * H + ko, H, tid);
            fill_copy(b + 32768, g_K16   + ((size_t)(bz * SQ + col0)) * H + ko, H, tid);
        }
        CP_COMMIT();
        fp++;
        if (++kb_f == NKB) { kb_f = 0; t_f += G; }
    };
    fill_step();
    fill_step();

    // Zero `out` for pv's atomic split-K reduction (hidden under MMA).
    {
        const int n4 = MTOT * H / 4;
        for (int i = blockIdx.x * NT + tid; i < n4; i += G * NT)
            ((float4*)outz)[i] = make_float4(0.f, 0.f, 0.f, 0.f);
    }

    float acc[2][8][4] = {};
    int cp = 0;
    const float scale = 0.03125f;  // 1/sqrt(1024)
    const int r0 = mw + (l >> 2), c0 = nw + (l & 3) * 2;

    for (int t = blockIdx.x; t < NTILES; t += G) {
        for (int kb = 0; kb < NKB; kb++) {
            fill_step();
            CP_WAIT2();
            __syncthreads();
            mma_k64_f16x2(sbuf + (uint32_t)(cp % 3) * STAGE_SC, aoff, boff, acc);
            __syncthreads();
            cp++;
        }
        int bz = t >> 10, rem = t & 1023;
        int row0 = (rem >> 5) << 7, col0 = (rem & 31) << 7;
        const size_t pbase = (size_t)bz * SQ * SQ;
        #pragma unroll
        for (int mf = 0; mf < 2; mf++)
            #pragma unroll
            for (int nf = 0; nf < 8; nf++)
                #pragma unroll
                for (int hh = 0; hh < 2; hh++) {
                    int r = row0 + r0 + mf * 16 + hh * 8;
                    int c = col0 + c0 + nf * 8;
                    size_t gi = pbase + (size_t)r * SQ + c;
                    int2 mk = __ldg((const int2*)(mask + gi));
                    float2 v;
                    v.x = (mk.x == 0) ? -CUDART_INF_F : acc[mf][nf][hh*2]     * scale;
                    v.y = (mk.y == 0) ? -CUDART_INF_F : acc[mf][nf][hh*2 + 1] * scale;
                    *(float2*)(g_P + gi) = v;
                    acc[mf][nf][hh*2] = 0.0f;
                    acc[mf][nf][hh*2 + 1] = 0.0f;
                }
    }
}

// ---------------------------------------------------------------------------
// Row softmax of g_P -> fp16 P. One block per row; row in registers.
// ---------------------------------------------------------------------------
__global__ __launch_bounds__(256) void softmax_k()
{
    __shared__ float red[8];
    const int tid = threadIdx.x;
    const float* p = g_P + (size_t)blockIdx.x * SQ;

    float4 v[4];
    float m = -CUDART_INF_F;
    #pragma unroll
    for (int i = 0; i < 4; i++) {
        v[i] = __ldg((const float4*)(p + (size_t)(i * 256 + tid) * 4));
        m = fmaxf(m, fmaxf(fmaxf(v[i].x, v[i].y), fmaxf(v[i].z, v[i].w)));
    }
    #pragma unroll
    for (int o = 16; o; o >>= 1) m = fmaxf(m, __shfl_xor_sync(0xFFFFFFFFu, m, o));
    if ((tid & 31) == 0) red[tid >> 5] = m;
    __syncthreads();
    m = fmaxf(fmaxf(fmaxf(red[0], red[1]), fmaxf(red[2], red[3])),
              fmaxf(fmaxf(red[4], red[5]), fmaxf(red[6], red[7])));
    __syncthreads();

    float s = 0.0f;
    #pragma unroll
    for (int i = 0; i < 4; i++) {
        v[i].x = __expf(v[i].x - m); v[i].y = __expf(v[i].y - m);
        v[i].z = __expf(v[i].z - m); v[i].w = __expf(v[i].w - m);
        s += (v[i].x + v[i].y) + (v[i].z + v[i].w);
    }
    #pragma unroll
    for (int o = 16; o; o >>= 1) s += __shfl_xor_sync(0xFFFFFFFFu, s, o);
    if ((tid & 31) == 0) red[tid >> 5] = s;
    __syncthreads();
    s = ((red[0] + red[1]) + (red[2] + red[3])) +
        ((red[4] + red[5]) + (red[6] + red[7]));
    float inv = 1.0f / s;

    size_t r2 = (size_t)blockIdx.x * (SQ / 2);
    #pragma unroll
    for (int i = 0; i < 4; i++) {
        int base = (i * 256 + tid) * 2;
        ((__half2*)g_P16)[r2 + base]     = __floats2half2_rn(v[i].x * inv, v[i].y * inv);
        ((__half2*)g_P16)[r2 + base + 1] = __floats2half2_rn(v[i].z * inv, v[i].w * inv);
    }
}

// ---------------------------------------------------------------------------
// PV: persistent 3-stage streamed fp16 GEMM with SPLIT-K-2.
// Single-term P(f16) x V(f16), fp32 accum. Atomic reduction into `out`.
// ---------------------------------------------------------------------------
__global__ __launch_bounds__(NT) void pv_mm(float* __restrict__ out)
{
    extern __shared__ char dsm[];
    uint32_t sbuf = smem_u32(dsm);
    const int tid = threadIdx.x, l = tid & 31, wid = tid >> 5;
    const int mw = (wid >> 1) * 32, nw = (wid & 1) * 64;
    const uint32_t aoff = (uint32_t)((mw + (l & 15)) * 128 + ((l >> 4) & 1) * 16);
    const uint32_t boff = (uint32_t)((nw + (l & 7) + ((l >> 4) & 1) * 8) * 128 +
                                     ((l >> 3) & 1) * 16);
    const int G = gridDim.x;
    const int NUNITS = (H / 128) * (SQ / 128) * NB * 2;  // 1024
    const int NKB = SQ / 128;                             // 32 k-blocks per unit

    int t_f = blockIdx.x, kb_f = 0, fp = 0;

    auto fill_step = [&]() {
        if (t_f < NUNITS) {
            int tt = t_f >> 1, kh = t_f & 1;
            int bz = tt >> 8, rem = tt & 255;
            int row0 = (rem >> 3) << 7, col0 = (rem & 7) << 7;
            size_t ko = (size_t)(kh * NKB + kb_f) * 64;
            uint32_t b = sbuf + (uint32_t)(fp % 3) * STAGE_PV;
            fill_copy(b,         g_P16  + (size_t)bz * SQ * SQ +
                                 (size_t)row0 * SQ + ko, SQ, tid);
            fill_copy(b + 16384, g_Vt16 + ((size_t)bz * H + col0) * SQ + ko, SQ, tid);
        }
        CP_COMMIT();
        fp++;
        if (++kb_f == NKB) { kb_f = 0; t_f += G; }
    };
    fill_step();
    fill_step();

    float acc[2][8][4] = {};
    int cp = 0;
    const int r0 = mw + (l >> 2), c0 = nw + (l & 3) * 2;

    for (int u = blockIdx.x; u < NUNITS; u += G) {
        for (int kb = 0; kb < NKB; kb++) {
            fill_step();
            CP_WAIT2();
            __syncthreads();
            mma_k64_f16(sbuf + (uint32_t)(cp % 3) * STAGE_PV, aoff, boff, acc);
            __syncthreads();
            cp++;
        }
        int tt = u >> 1;
        int bz = tt >> 8, rem = tt & 255;
        int row0 = (rem >> 3) << 7, col0 = (rem & 7) << 7;
        #pragma unroll
        for (int mf = 0; mf < 2; mf++)
            #pragma unroll
            for (int nf = 0; nf < 8; nf++)
                #pragma unroll
                for (int hh = 0; hh < 2; hh++) {
                    int r = row0 + r0 + mf * 16 + hh * 8;
                    int c = col0 + c0 + nf * 8;
                    float* o = &out[((size_t)bz * SQ + r) * H + c];
                    atomicAdd(o,     acc[mf][nf][hh*2]);
                    atomicAdd(o + 1, acc[mf][nf][hh*2 + 1]);
                    acc[mf][nf][hh*2] = 0.0f;
                    acc[mf][nf][hh*2 + 1] = 0.0f;
                }
    }
}

// ---------------------------------------------------------------------------
extern "C" void kernel_launch(void* const* d_in, const int* in_sizes, int n_in,
                              void* d_out, int out_size)
{
    const float* X    = (const float*)d_in[0];
    const int*   mask = (const int*)  d_in[1];
    const float* Wq   = (const float*)d_in[2];
    const float* bq   = (const float*)d_in[3];
    const float* Wk   = (const float*)d_in[4];
    const float* bk   = (const float*)d_in[5];
    const float* Wv   = (const float*)d_in[6];
    const float* bv   = (const float*)d_in[7];
    float* out = (float*)d_out;

    cudaFuncSetAttribute(qkv_mm,    cudaFuncAttributeMaxDynamicSharedMemorySize, SMEM_QKV);
    cudaFuncSetAttribute(scores_mm, cudaFuncAttributeMaxDynamicSharedMemorySize, SMEM_SC);
    cudaFuncSetAttribute(pv_mm,     cudaFuncAttributeMaxDynamicSharedMemorySize, SMEM_PV);

    int dev = 0, nsm = 148;
    cudaGetDevice(&dev);
    cudaDeviceGetAttribute(&nsm, cudaDevAttrMultiProcessorCount, dev);

    int total4 = (MTOT * E + 3 * H * E) / 4;
    split_k<<<total4 / NT, NT>>>(X, Wq, Wk, Wv);

    qkv_mm<<<dim3(H / 128, MTOT / 128, 3), NT, SMEM_QKV>>>(bq, bk, bv);
    scores_mm<<<nsm, NT, SMEM_SC>>>(mask, out);
    softmax_k<<<NB * SQ, 256>>>();
    pv_mm<<<nsm, NT, SMEM_PV>>>(out);
}